// round 7
// baseline (speedup 1.0000x reference)
#include <cuda_runtime.h>
#include <cuda_bf16.h>
#include <math.h>
#include <stdint.h>

#define BB 32
#define SC 128
#define NM 16
#define DM 512
#define HH 8
#define DH 64
#define NC 39998
#define MQ (BB*NM)    /* 512 gathered query rows */
#define KP2 256       /* packed pairs per row (DM/2) */
#define NCHUNK 313    /* ceil(NC/128) */

// ---------------- scratch (device globals; no allocation allowed) -------------
__device__ float g_curr[BB*SC*DM];
__device__ float g_KV[BB*SC*1024];     // K cols 0..511, V cols 512..1023
__device__ float g_Q[MQ*DM];
__device__ float g_attn[MQ*DM];
__device__ float g_bKV[1024];
__device__ float2 g_part[NCHUNK*MQ];   // per (chunk,row) partial (max, sumexp)
__device__ float g_lse[MQ];

// packed bf16 hi/lo operands
__device__ unsigned g_pk_currH[BB*SC*KP2];
__device__ unsigned g_pk_currL[BB*SC*KP2];
__device__ unsigned g_pk_wkvH[1024*KP2];
__device__ unsigned g_pk_wkvL[1024*KP2];
__device__ unsigned g_pk_wqH[DM*KP2];
__device__ unsigned g_pk_wqL[DM*KP2];
__device__ unsigned g_pk_t2H[DM*KP2];
__device__ unsigned g_pk_t2L[DM*KP2];
__device__ unsigned g_pk_qinH[MQ*KP2];
__device__ unsigned g_pk_qinL[MQ*KP2];
__device__ unsigned g_pk_tanhH[MQ*KP2];
__device__ unsigned g_pk_tanhL[MQ*KP2];
__device__ unsigned g_pk_hybH[MQ*KP2];
__device__ unsigned g_pk_hybL[MQ*KP2];

// ---------------- bf16 split helper ------------------------------------------
__device__ __forceinline__ void split_pack(float x, float y,
                                           unsigned& hi, unsigned& lo) {
    __nv_bfloat16 hx = __float2bfloat16_rn(x);
    __nv_bfloat16 hy = __float2bfloat16_rn(y);
    float rx = x - __bfloat162float(hx);
    float ry = y - __bfloat162float(hy);
    __nv_bfloat16 lx = __float2bfloat16_rn(rx);
    __nv_bfloat16 ly = __float2bfloat16_rn(ry);
    hi = ((unsigned)__bfloat16_as_ushort(hy) << 16) | __bfloat16_as_ushort(hx);
    lo = ((unsigned)__bfloat16_as_ushort(ly) << 16) | __bfloat16_as_ushort(lx);
}

// ---------------- small elementwise kernels -----------------------------------
__global__ void concat_bias_kernel(const float* __restrict__ bk,
                                   const float* __restrict__ bv,
                                   float* __restrict__ out) {
    int t = blockIdx.x * blockDim.x + threadIdx.x;
    if (t < 512) out[t] = bk[t];
    else if (t < 1024) out[t] = bv[t - 512];
}

// gather + positional embedding; emits f32 curr AND packed hi/lo
__global__ void gather_pe_pack_kernel(const int* __restrict__ idx,
                                      const float* __restrict__ emb,
                                      float* __restrict__ out,
                                      unsigned* __restrict__ H,
                                      unsigned* __restrict__ L) {
    int i = blockIdx.x * blockDim.x + threadIdx.x;     // pair index
    if (i >= BB * SC * KP2) return;
    int pp  = i & (KP2 - 1);
    int row = i / KP2;
    int s   = row & (SC - 1);
    int g   = idx[row];
    int d0  = pp * 2;
    float freq = expf((float)d0 * -0.0179889460176f);  // -ln(10000)/512
    float ang  = (float)s * freq;
    float v0 = emb[(size_t)g * DM + d0]     + sinf(ang);
    float v1 = emb[(size_t)g * DM + d0 + 1] + cosf(ang);
    ((float2*)out)[i] = make_float2(v0, v1);
    split_pack(v0, v1, H[i], L[i]);
}

// gather packed rows of curr at mask positions
__global__ void gather_qpk_kernel(const int* __restrict__ mask_pos,
                                  const unsigned* __restrict__ cH,
                                  const unsigned* __restrict__ cL,
                                  unsigned* __restrict__ qH,
                                  unsigned* __restrict__ qL) {
    int i = blockIdx.x * blockDim.x + threadIdx.x;
    if (i >= MQ * KP2) return;
    int c = i & (KP2 - 1);
    int r = i / KP2;
    int b = r / NM;
    int p = mask_pos[r];
    size_t src = ((size_t)b * SC + p) * KP2 + c;
    qH[i] = cH[src];
    qL[i] = cL[src];
}

__global__ void prepack_kernel(const float* __restrict__ in,
                               unsigned* __restrict__ H,
                               unsigned* __restrict__ L,
                               long npairs, int do_tanh) {
    long i = (long)blockIdx.x * blockDim.x + threadIdx.x;
    if (i >= npairs) return;
    float2 v = ((const float2*)in)[i];
    if (do_tanh) { v.x = tanhf(v.x); v.y = tanhf(v.y); }
    split_pack(v.x, v.y, H[i], L[i]);
}

// ---------------- mma / ldmatrix / cp.async helpers ----------------------------
__device__ __forceinline__ void mma_bf16(float* c, const unsigned* a, const unsigned* b) {
    asm("mma.sync.aligned.m16n8k16.row.col.f32.bf16.bf16.f32 "
        "{%0,%1,%2,%3}, {%4,%5,%6,%7}, {%8,%9}, {%0,%1,%2,%3};"
        : "+f"(c[0]), "+f"(c[1]), "+f"(c[2]), "+f"(c[3])
        : "r"(a[0]), "r"(a[1]), "r"(a[2]), "r"(a[3]), "r"(b[0]), "r"(b[1]));
}
__device__ __forceinline__ void cp16(void* dst, const void* src, bool ok) {
    unsigned d = (unsigned)__cvta_generic_to_shared(dst);
    int sz = ok ? 16 : 0;
    asm volatile("cp.async.cg.shared.global [%0], [%1], 16, %2;"
                 :: "r"(d), "l"(src), "r"(sz));
}
#define LDSM4(r, a)                                                          \
    asm volatile("ldmatrix.sync.aligned.m8n8.x4.shared.b16 {%0,%1,%2,%3}, [%4];" \
                 : "=r"((r)[0]), "=r"((r)[1]), "=r"((r)[2]), "=r"((r)[3])    \
                 : "r"(a))

#define PITCH 20
#define TSZ (128*PITCH)

// ======== fragment-load + mma block shared by all GEMM variants ==============
#define MMA_STEP(baseAH, baseAL, baseBH, baseBL)                                 \
    _Pragma("unroll")                                                            \
    for (int ks = 0; ks < 2; ++ks) {                                             \
        int kc = ks * 8;                                                         \
        unsigned ah[4][4], al[4][4];                                             \
        _Pragma("unroll")                                                        \
        for (int mt = 0; mt < 4; ++mt) {                                         \
            uint32_t off = (uint32_t)(((a_row + mt * 16) * PITCH + kc + a_col) * 4); \
            LDSM4(ah[mt], (baseAH) + off);                                       \
            LDSM4(al[mt], (baseAL) + off);                                       \
        }                                                                        \
        unsigned bh[4][2], bl[4][2];                                             \
        _Pragma("unroll")                                                        \
        for (int np = 0; np < 2; ++np) {                                         \
            uint32_t off = (uint32_t)(((b_row + np * 16) * PITCH + kc + b_col) * 4); \
            unsigned rh[4], rl[4];                                               \
            LDSM4(rh, (baseBH) + off);                                           \
            LDSM4(rl, (baseBL) + off);                                           \
            bh[np * 2][0]     = rh[0]; bh[np * 2][1]     = rh[1];                \
            bh[np * 2 + 1][0] = rh[2]; bh[np * 2 + 1][1] = rh[3];                \
            bl[np * 2][0]     = rl[0]; bl[np * 2][1]     = rl[1];                \
            bl[np * 2 + 1][0] = rl[2]; bl[np * 2 + 1][1] = rl[3];                \
        }                                                                        \
        _Pragma("unroll")                                                        \
        for (int mt = 0; mt < 4; ++mt)                                           \
            _Pragma("unroll")                                                    \
            for (int nt = 0; nt < 4; ++nt) {                                     \
                mma_bf16(acc[mt][nt], ah[mt], bh[nt]);                           \
                mma_bf16(acc[mt][nt], al[mt], bh[nt]);                           \
                mma_bf16(acc[mt][nt], ah[mt], bl[nt]);                           \
            }                                                                    \
    }

#define GEMM_PROLOG()                                                            \
    int bm = blockIdx.x * 128;                                                   \
    int bn = blockIdx.y * 128;                                                   \
    int tid = threadIdx.x;                                                       \
    int wid = tid >> 5;                                                          \
    int lane = tid & 31;                                                         \
    int warp_m = wid >> 2;                                                       \
    int warp_n = wid & 3;                                                        \
    int g  = lane >> 2;                                                          \
    int tg = lane & 3;                                                           \
    int m_base = warp_m * 64;                                                    \
    int n_base = warp_n * 32;                                                    \
    int a_row = m_base + (lane & 15);                                            \
    int a_col = (lane >> 4) * 4;                                                 \
    int b_row = n_base + ((lane >> 4) & 1) * 8 + (lane & 7);                     \
    int b_col = ((lane >> 3) & 1) * 4;                                           \
    float acc[4][4][4];                                                          \
    _Pragma("unroll")                                                            \
    for (int mt = 0; mt < 4; ++mt)                                               \
        _Pragma("unroll")                                                        \
        for (int nt = 0; nt < 4; ++nt)                                           \
            _Pragma("unroll")                                                    \
            for (int i = 0; i < 4; ++i) acc[mt][nt][i] = 0.f;                    \
    int srow0 = tid >> 2;                                                        \
    int sc4   = (tid & 3) * 4;                                                   \
    int srow1 = (tid + 256) >> 2;

#define STAGE_PK(buf, k0p)                                                       \
    {                                                                            \
        unsigned* bAH = sm + (buf) * 4 * TSZ;                                    \
        unsigned* bAL = bAH + TSZ;                                               \
        unsigned* bBH = bAH + 2 * TSZ;                                           \
        unsigned* bBL = bAH + 3 * TSZ;                                           \
        _Pragma("unroll")                                                        \
        for (int i = 0; i < 2; ++i) {                                            \
            int row = i ? srow1 : srow0;                                         \
            cp16(bAH + row * PITCH + sc4, AH + (size_t)(bm + row) * KP2 + (k0p) + sc4, true); \
            cp16(bAL + row * PITCH + sc4, AL + (size_t)(bm + row) * KP2 + (k0p) + sc4, true); \
            int nrow = bn + row;                                                 \
            bool ok = nrow < N;                                                  \
            size_t bro = (size_t)(ok ? nrow : 0) * KP2 + (k0p) + sc4;            \
            cp16(bBH + row * PITCH + sc4, BH + bro, ok);                         \
            cp16(bBL + row * PITCH + sc4, BL + bro, ok);                         \
        }                                                                        \
        asm volatile("cp.async.commit_group;");                                  \
    }

// ---------------- GEMM variant 1: packed A, packed B, f32 C + bias -------------
__global__ __launch_bounds__(256)
void gemm_pk_kernel(const unsigned* __restrict__ AH, const unsigned* __restrict__ AL,
                    const unsigned* __restrict__ BH, const unsigned* __restrict__ BL,
                    const float* __restrict__ bias,
                    float* __restrict__ C,
                    int M, int N, int ldc) {
    extern __shared__ unsigned sm[];
    uint32_t smem_u32 = (uint32_t)__cvta_generic_to_shared(sm);
    GEMM_PROLOG();

    STAGE_PK(0, 0);
    const int NSTEP = DM / 32;
    for (int s = 0; s < NSTEP; ++s) {
        if (s + 1 < NSTEP) {
            STAGE_PK((s + 1) & 1, (s + 1) * 16);
            asm volatile("cp.async.wait_group 1;");
        } else {
            asm volatile("cp.async.wait_group 0;");
        }
        __syncthreads();
        uint32_t baseAH = smem_u32 + ((s & 1) * 4 * TSZ) * 4;
        MMA_STEP(baseAH, baseAH + TSZ * 4, baseAH + 2 * TSZ * 4, baseAH + 3 * TSZ * 4);
        __syncthreads();
    }

#pragma unroll
    for (int mt = 0; mt < 4; ++mt) {
        int row0 = bm + m_base + mt * 16 + g;
#pragma unroll
        for (int nt = 0; nt < 4; ++nt) {
            int col0 = bn + n_base + nt * 8 + 2 * tg;
            float b0 = bias ? bias[col0] : 0.f;
            float b1 = bias ? bias[col0 + 1] : 0.f;
            C[(size_t)row0 * ldc + col0]           = acc[mt][nt][0] + b0;
            C[(size_t)row0 * ldc + col0 + 1]       = acc[mt][nt][1] + b1;
            C[(size_t)(row0 + 8) * ldc + col0]     = acc[mt][nt][2] + b0;
            C[(size_t)(row0 + 8) * ldc + col0 + 1] = acc[mt][nt][3] + b1;
        }
    }
}

// ---------------- GEMM variant 2: packed A/B, packed-out C (for t2) -----------
__global__ __launch_bounds__(256)
void gemm_pk_packout_kernel(const unsigned* __restrict__ AH, const unsigned* __restrict__ AL,
                            const unsigned* __restrict__ BH, const unsigned* __restrict__ BL,
                            const float* __restrict__ bias,
                            unsigned* __restrict__ CH, unsigned* __restrict__ CL,
                            int M, int N) {
    extern __shared__ unsigned sm[];
    uint32_t smem_u32 = (uint32_t)__cvta_generic_to_shared(sm);
    GEMM_PROLOG();

    STAGE_PK(0, 0);
    const int NSTEP = DM / 32;
    for (int s = 0; s < NSTEP; ++s) {
        if (s + 1 < NSTEP) {
            STAGE_PK((s + 1) & 1, (s + 1) * 16);
            asm volatile("cp.async.wait_group 1;");
        } else {
            asm volatile("cp.async.wait_group 0;");
        }
        __syncthreads();
        uint32_t baseAH = smem_u32 + ((s & 1) * 4 * TSZ) * 4;
        MMA_STEP(baseAH, baseAH + TSZ * 4, baseAH + 2 * TSZ * 4, baseAH + 3 * TSZ * 4);
        __syncthreads();
    }

#pragma unroll
    for (int mt = 0; mt < 4; ++mt) {
        int row0 = bm + m_base + mt * 16 + g;
#pragma unroll
        for (int nt = 0; nt < 4; ++nt) {
            int col0 = bn + n_base + nt * 8 + 2 * tg;
            float b0 = bias[col0], b1 = bias[col0 + 1];
            float v0 = acc[mt][nt][0] + b0, v1 = acc[mt][nt][1] + b1;
            float v2 = acc[mt][nt][2] + b0, v3 = acc[mt][nt][3] + b1;
            size_t p0 = (size_t)row0 * KP2 + (col0 >> 1);
            size_t p1 = (size_t)(row0 + 8) * KP2 + (col0 >> 1);
            split_pack(v0, v1, CH[p0], CL[p0]);
            split_pack(v2, v3, CH[p1], CL[p1]);
        }
    }
}

// ---------------- GEMM variant 3: packed A, f32 B (emb), C + LSE partials ------
#define BPITCH 36
#define BF32U (128*BPITCH)                  /* uint32 (=floats) */
#define BUFU (4*TSZ + BF32U)                /* uint32 per buffer */
__global__ __launch_bounds__(256)
void gemm_score_kernel(const unsigned* __restrict__ AH, const unsigned* __restrict__ AL,
                       const float* __restrict__ Bf,   // emb+2*DM, rows of 512 f32
                       float* __restrict__ C,
                       float2* __restrict__ part,
                       int N) {
    extern __shared__ unsigned sm[];
    uint32_t smem_u32 = (uint32_t)__cvta_generic_to_shared(sm);
    GEMM_PROLOG();
    (void)srow1;
    int brow = tid >> 3;          // B f32 staging: 0..31 (+32 per chunk)
    int bq   = (tid & 7) * 4;     // float col within 32

    // stage: A packed (2 chunks) + B f32 (4 chunks)
#define STAGE_SC(buf, s)                                                         \
    {                                                                            \
        unsigned* bAH = sm + (buf) * BUFU;                                       \
        unsigned* bAL = bAH + TSZ;                                               \
        float*    bF  = (float*)(bAH + 4 * TSZ);                                 \
        int k0p = (s) * 16;                                                      \
        _Pragma("unroll")                                                        \
        for (int i = 0; i < 2; ++i) {                                            \
            int row = (i ? srow1 : srow0);                                       \
            cp16(bAH + row * PITCH + sc4, AH + (size_t)(bm + row) * KP2 + k0p + sc4, true); \
            cp16(bAL + row * PITCH + sc4, AL + (size_t)(bm + row) * KP2 + k0p + sc4, true); \
        }                                                                        \
        _Pragma("unroll")                                                        \
        for (int j = 0; j < 4; ++j) {                                            \
            int row = brow + j * 32;                                             \
            int nrow = bn + row;                                                 \
            bool ok = nrow < N;                                                  \
            cp16(bF + row * BPITCH + bq,                                         \
                 Bf + (size_t)(ok ? nrow : 0) * DM + (s) * 32 + bq, ok);         \
        }                                                                        \
        asm volatile("cp.async.commit_group;");                                  \
    }

    STAGE_SC(0, 0);
    const int NSTEP = DM / 32;
    for (int s = 0; s < NSTEP; ++s) {
        if (s + 1 < NSTEP) {
            STAGE_SC((s + 1) & 1, s + 1);
            asm volatile("cp.async.wait_group 1;");
        } else {
            asm volatile("cp.async.wait_group 0;");
        }
        __syncthreads();

        // convert B f32 -> packed hi/lo in smem (free issue slots)
        unsigned* bAH = sm + (s & 1) * BUFU;
        unsigned* bBH = bAH + 2 * TSZ;
        unsigned* bBL = bAH + 3 * TSZ;
        float*    bF  = (float*)(bAH + 4 * TSZ);
#pragma unroll
        for (int j = 0; j < 8; ++j) {
            int idx = tid + j * 256;
            int row = idx >> 4;
            int p   = idx & 15;
            float x = bF[row * BPITCH + 2 * p];
            float y = bF[row * BPITCH + 2 * p + 1];
            split_pack(x, y, bBH[row * PITCH + p], bBL[row * PITCH + p]);
        }
        __syncthreads();

        uint32_t baseAH = smem_u32 + ((s & 1) * BUFU) * 4;
        MMA_STEP(baseAH, baseAH + TSZ * 4, baseAH + 2 * TSZ * 4, baseAH + 3 * TSZ * 4);
        __syncthreads();
    }

    // epilogue: store C + per-row (max, sumexp) partials
    float2* red = (float2*)sm;     // [128][16]
#pragma unroll
    for (int mt = 0; mt < 4; ++mt) {
        int rl0 = m_base + mt * 16 + g;
        int row0 = bm + rl0;
        float m0 = -INFINITY, s0 = 0.f, m1 = -INFINITY, s1 = 0.f;
#pragma unroll
        for (int nt = 0; nt < 4; ++nt) {
            int col0 = bn + n_base + nt * 8 + 2 * tg;
            float v00 = acc[mt][nt][0], v01 = acc[mt][nt][1];
            float v10 = acc[mt][nt][2], v11 = acc[mt][nt][3];
            if (col0 < N) {
                C[(size_t)row0 * N + col0]       = v00;
                C[(size_t)(row0 + 8) * N + col0] = v10;
                float nm0 = fmaxf(m0, v00); s0 = s0 * __expf(m0 - nm0) + __expf(v00 - nm0); m0 = nm0;
                float nm1 = fmaxf(m1, v10); s1 = s1 * __expf(m1 - nm1) + __expf(v10 - nm1); m1 = nm1;
            }
            if (col0 + 1 < N) {
                C[(size_t)row0 * N + col0 + 1]       = v01;
                C[(size_t)(row0 + 8) * N + col0 + 1] = v11;
                float nm0 = fmaxf(m0, v01); s0 = s0 * __expf(m0 - nm0) + __expf(v01 - nm0); m0 = nm0;
                float nm1 = fmaxf(m1, v11); s1 = s1 * __expf(m1 - nm1) + __expf(v11 - nm1); m1 = nm1;
            }
        }
        int slot = warp_n * 4 + tg;
        red[rl0 * 16 + slot]       = make_float2(m0, s0);
        red[(rl0 + 8) * 16 + slot] = make_float2(m1, s1);
    }
    __syncthreads();
    if (tid < 128) {
        float m = -INFINITY, s = 0.f;
#pragma unroll
        for (int k = 0; k < 16; ++k) {
            float2 v = red[tid * 16 + k];
            float nm = fmaxf(m, v.x);
            s = s * __expf(m - nm) + v.y * __expf(v.x - nm);
            m = nm;
        }
        part[(size_t)blockIdx.y * MQ + bm + tid] = make_float2(m, s);
    }
}

// ---------------- attention (reads merged KV, ldc=1024) -----------------------
__global__ __launch_bounds__(256)
void attn_kernel(const float* __restrict__ Q,
                 const float* __restrict__ KV,
                 float* __restrict__ out) {
    int blk = blockIdx.x;
    int b = blk / HH, h = blk % HH;

    __shared__ float sQ[NM][DH];
    __shared__ float sS[NM][SC];
    __shared__ float sKV[SC][DH + 1];

    int tid = threadIdx.x;

    for (int e = tid; e < NM * DH; e += 256) {
        int m = e / DH, d0 = e % DH;
        sQ[m][d0] = Q[((size_t)b * NM + m) * DM + h * DH + d0];
    }
    for (int e = tid; e < SC * DH; e += 256) {
        int k = e / DH, d0 = e % DH;
        sKV[k][d0] = KV[((size_t)b * SC + k) * 1024 + h * DH + d0];
    }
    __syncthreads();

    for (int e = tid; e < NM * SC; e += 256) {
        int m = e / SC, k = e % SC;
        float acc = 0.f;
#pragma unroll
        for (int d0 = 0; d0 < DH; ++d0) acc += sQ[m][d0] * sKV[k][d0];
        sS[m][k] = acc;
    }
    __syncthreads();

    int w = tid >> 5, lane = tid & 31;
    for (int m = 2 * w; m < 2 * w + 2; ++m) {
        float vals[4];
        float mx = -INFINITY;
#pragma unroll
        for (int j = 0; j < 4; ++j) {
            vals[j] = sS[m][lane * 4 + j];
            mx = fmaxf(mx, vals[j]);
        }
#pragma unroll
        for (int off = 16; off; off >>= 1)
            mx = fmaxf(mx, __shfl_xor_sync(0xffffffffu, mx, off));
        float sum = 0.f;
#pragma unroll
        for (int j = 0; j < 4; ++j) {
            vals[j] = expf(vals[j] - mx);
            sum += vals[j];
        }
#pragma unroll
        for (int off = 16; off; off >>= 1)
            sum += __shfl_xor_sync(0xffffffffu, sum, off);
        float inv = 1.f / sum;
#pragma unroll
        for (int j = 0; j < 4; ++j) sS[m][lane * 4 + j] = vals[j] * inv;
    }
    __syncthreads();

    for (int e = tid; e < SC * DH; e += 256) {
        int k = e / DH, d0 = e % DH;
        sKV[k][d0] = KV[((size_t)b * SC + k) * 1024 + 512 + h * DH + d0];
    }
    __syncthreads();

    for (int e = tid; e < NM * DH; e += 256) {
        int m = e / DH, d0 = e % DH;
        float acc = 0.f;
#pragma unroll
        for (int k = 0; k < SC; ++k) acc += sS[m][k] * sKV[k][d0];
        out[((size_t)b * NM + m) * DM + h * DH + d0] = acc;
    }
}

// ---------------- LSE reduce + subtract ---------------------------------------
__global__ void lse_reduce_kernel(const float2* __restrict__ part,
                                  float* __restrict__ lse) {
    int row = blockIdx.x;
    int lane = threadIdx.x;
    float m = -INFINITY, s = 0.f;
    for (int c = lane; c < NCHUNK; c += 32) {
        float2 v = part[(size_t)c * MQ + row];
        float nm = fmaxf(m, v.x);
        s = s * __expf(m - nm) + v.y * __expf(v.x - nm);
        m = nm;
    }
#pragma unroll
    for (int off = 16; off; off >>= 1) {
        float m2 = __shfl_xor_sync(0xffffffffu, m, off);
        float s2 = __shfl_xor_sync(0xffffffffu, s, off);
        float nm = fmaxf(m, m2);
        s = s * __expf(m - nm) + s2 * __expf(m2 - nm);
        m = nm;
    }
    if (lane == 0) lse[row] = m + logf(s);
}

__global__ __launch_bounds__(256)
void subtract_kernel(float* __restrict__ out, const float* __restrict__ lse) {
    int row = blockIdx.x;
    float l = lse[row];
    float* p = out + (size_t)row * NC;
    for (int i = threadIdx.x; i < NC; i += 256) p[i] -= l;
}

// ---------------- launch -----------------------------------------------------
extern "C" void kernel_launch(void* const* d_in, const int* in_sizes, int n_in,
                              void* d_out, int out_size) {
    const int*   mask_pos  = (const int*)d_in[2];
    const int*   mask_curr = (const int*)d_in[3];
    const float* emb       = (const float*)d_in[5];
    const float* c_wq = (const float*)d_in[12];
    const float* c_bq = (const float*)d_in[13];
    const float* c_wk = (const float*)d_in[14];
    const float* c_bk = (const float*)d_in[15];
    const float* c_wv = (const float*)d_in[16];
    const float* c_bv = (const float*)d_in[17];
    const float* t2_w = (const float*)d_in[24];
    const float* t2_b = (const float*)d_in[25];
    float* out = (float*)d_out;

    float *curr, *KV, *Qb, *attn, *bKV, *lse;
    float2* part;
    cudaGetSymbolAddress((void**)&curr, g_curr);
    cudaGetSymbolAddress((void**)&KV,   g_KV);
    cudaGetSymbolAddress((void**)&Qb,   g_Q);
    cudaGetSymbolAddress((void**)&attn, g_attn);
    cudaGetSymbolAddress((void**)&bKV,  g_bKV);
    cudaGetSymbolAddress((void**)&part, g_part);
    cudaGetSymbolAddress((void**)&lse,  g_lse);

    unsigned *currH, *currL, *wkvH, *wkvL, *wqH, *wqL, *t2H, *t2L;
    unsigned *qinH, *qinL, *tanhH, *tanhL, *hybH, *hybL;
    cudaGetSymbolAddress((void**)&currH, g_pk_currH);
    cudaGetSymbolAddress((void**)&currL, g_pk_currL);
    cudaGetSymbolAddress((void**)&wkvH,  g_pk_wkvH);
    cudaGetSymbolAddress((void**)&wkvL,  g_pk_wkvL);
    cudaGetSymbolAddress((void**)&wqH,   g_pk_wqH);
    cudaGetSymbolAddress((void**)&wqL,   g_pk_wqL);
    cudaGetSymbolAddress((void**)&t2H,   g_pk_t2H);
    cudaGetSymbolAddress((void**)&t2L,   g_pk_t2L);
    cudaGetSymbolAddress((void**)&qinH,  g_pk_qinH);
    cudaGetSymbolAddress((void**)&qinL,  g_pk_qinL);
    cudaGetSymbolAddress((void**)&tanhH, g_pk_tanhH);
    cudaGetSymbolAddress((void**)&tanhL, g_pk_tanhL);
    cudaGetSymbolAddress((void**)&hybH,  g_pk_hybH);
    cudaGetSymbolAddress((void**)&hybL,  g_pk_hybL);

    const int SMEMB  = 2 * 4 * TSZ * 4;    // 81920 B (pk kernels)
    const int SMEMSC = 2 * BUFU * 4;       // 118784 B (score kernel)
    cudaFuncSetAttribute(gemm_pk_kernel,
                         cudaFuncAttributeMaxDynamicSharedMemorySize, SMEMB);
    cudaFuncSetAttribute(gemm_pk_packout_kernel,
                         cudaFuncAttributeMaxDynamicSharedMemorySize, SMEMB);
    cudaFuncSetAttribute(gemm_score_kernel,
                         cudaFuncAttributeMaxDynamicSharedMemorySize, SMEMSC);

    const long WP = (long)DM * KP2;        // pairs per 512x512 matrix

    // 1. weight prepacks + bias concat
    prepack_kernel<<<(int)((WP + 255) / 256), 256>>>(c_wk, wkvH,      wkvL,      WP, 0);
    prepack_kernel<<<(int)((WP + 255) / 256), 256>>>(c_wv, wkvH + WP, wkvL + WP, WP, 0);
    prepack_kernel<<<(int)((WP + 255) / 256), 256>>>(c_wq, wqH,       wqL,       WP, 0);
    prepack_kernel<<<(int)((WP + 255) / 256), 256>>>(t2_w, t2H,       t2L,       WP, 0);
    concat_bias_kernel<<<4, 256>>>(c_bk, c_bv, bKV);

    // 2. curr = emb[mask_curr] + PE (f32 + packed)
    gather_pe_pack_kernel<<<(BB * SC * KP2 + 255) / 256, 256>>>(mask_curr, emb,
                                                                curr, currH, currL);

    // 3. merged K|V projection: [4096, 1024]
    {
        dim3 g((BB * SC) / 128, 1024 / 128);
        gemm_pk_kernel<<<g, 256, SMEMB>>>(currH, currL, wkvH, wkvL, bKV, KV,
                                          BB * SC, 1024, 1024);
    }

    // 4. Q projection over the 512 gathered rows (packed gather, no f32 pass)
    gather_qpk_kernel<<<(MQ * KP2 + 255) / 256, 256>>>(mask_pos, currH, currL, qinH, qinL);
    {
        dim3 g(MQ / 128, DM / 128);
        gemm_pk_kernel<<<g, 256, SMEMB>>>(qinH, qinL, wqH, wqL, c_bq, Qb, MQ, DM, DM);
    }

    // 5. attention
    attn_kernel<<<BB * HH, 256>>>(Qb, KV, attn);

    // 6. hyb = tanh(attn) @ t2_w^T + t2_b, emitted directly as packed hi/lo
    prepack_kernel<<<(MQ * KP2 + 255) / 256, 256>>>(attn, tanhH, tanhL, MQ * KP2, 1);
    {
        dim3 g(MQ / 128, DM / 128);
        gemm_pk_packout_kernel<<<g, 256, SMEMB>>>(tanhH, tanhL, t2H, t2L, t2_b,
                                                  hybH, hybL, MQ, DM);
    }

    // 7. scores = hyb @ emb[2:]^T with fused in-kernel B conversion + LSE partials
    {
        dim3 g(MQ / 128, NCHUNK);
        gemm_score_kernel<<<g, 256, SMEMSC>>>(hybH, hybL, emb + 2 * DM, out, part, NC);
    }

    // 8. lse reduce + subtract
    lse_reduce_kernel<<<MQ, 32>>>(part, lse);
    subtract_kernel<<<MQ, 256>>>(out, lse);
}

// round 8
// speedup vs baseline: 1.0468x; 1.0468x over previous
#include <cuda_runtime.h>
#include <cuda_bf16.h>
#include <math.h>
#include <stdint.h>

#define BB 32
#define SC 128
#define NM 16
#define DM 512
#define HH 8
#define DH 64
#define NC 39998
#define MQ (BB*NM)    /* 512 gathered query rows */
#define KP2 256       /* packed pairs per row (DM/2) */
#define NCHUNK 313    /* ceil(NC/128) */

// ---------------- scratch (device globals; no allocation allowed) -------------
__device__ float g_KV[BB*SC*1024];     // K cols 0..511, V cols 512..1023
__device__ float g_Q[MQ*DM];
__device__ float g_attn[MQ*DM];
__device__ float g_bKV[1024];
__device__ float2 g_part[NCHUNK*MQ];   // per (chunk,row) partial (max, sumexp)
__device__ float g_lse[MQ];

// packed bf16 hi/lo operands
__device__ unsigned g_pk_embH[(size_t)NC*KP2];
__device__ unsigned g_pk_embL[(size_t)NC*KP2];
__device__ unsigned g_pk_currH[BB*SC*KP2];
__device__ unsigned g_pk_currL[BB*SC*KP2];
__device__ unsigned g_pk_wkvH[1024*KP2];
__device__ unsigned g_pk_wkvL[1024*KP2];
__device__ unsigned g_pk_wqH[DM*KP2];
__device__ unsigned g_pk_wqL[DM*KP2];
__device__ unsigned g_pk_t2H[DM*KP2];
__device__ unsigned g_pk_t2L[DM*KP2];
__device__ unsigned g_pk_qinH[MQ*KP2];
__device__ unsigned g_pk_qinL[MQ*KP2];
__device__ unsigned g_pk_tanhH[MQ*KP2];
__device__ unsigned g_pk_tanhL[MQ*KP2];
__device__ unsigned g_pk_hybH[MQ*KP2];
__device__ unsigned g_pk_hybL[MQ*KP2];

// ---------------- bf16 split helper ------------------------------------------
__device__ __forceinline__ void split_pack(float x, float y,
                                           unsigned& hi, unsigned& lo) {
    __nv_bfloat16 hx = __float2bfloat16_rn(x);
    __nv_bfloat16 hy = __float2bfloat16_rn(y);
    float rx = x - __bfloat162float(hx);
    float ry = y - __bfloat162float(hy);
    __nv_bfloat16 lx = __float2bfloat16_rn(rx);
    __nv_bfloat16 ly = __float2bfloat16_rn(ry);
    hi = ((unsigned)__bfloat16_as_ushort(hy) << 16) | __bfloat16_as_ushort(hx);
    lo = ((unsigned)__bfloat16_as_ushort(ly) << 16) | __bfloat16_as_ushort(lx);
}

// ---------------- small elementwise kernels -----------------------------------
__global__ void concat_bias_kernel(const float* __restrict__ bk,
                                   const float* __restrict__ bv,
                                   float* __restrict__ out) {
    int t = blockIdx.x * blockDim.x + threadIdx.x;
    if (t < 512) out[t] = bk[t];
    else if (t < 1024) out[t] = bv[t - 512];
}

// gather + positional embedding; emits packed hi/lo directly
__global__ void gather_pe_pack_kernel(const int* __restrict__ idx,
                                      const float* __restrict__ emb,
                                      unsigned* __restrict__ H,
                                      unsigned* __restrict__ L) {
    int i = blockIdx.x * blockDim.x + threadIdx.x;     // pair index
    if (i >= BB * SC * KP2) return;
    int pp  = i & (KP2 - 1);
    int row = i / KP2;
    int s   = row & (SC - 1);
    int g   = idx[row];
    int d0  = pp * 2;
    float freq = expf((float)d0 * -0.0179889460176f);  // -ln(10000)/512
    float ang  = (float)s * freq;
    float v0 = emb[(size_t)g * DM + d0]     + sinf(ang);
    float v1 = emb[(size_t)g * DM + d0 + 1] + cosf(ang);
    split_pack(v0, v1, H[i], L[i]);
}

// gather packed rows of curr at mask positions
__global__ void gather_qpk_kernel(const int* __restrict__ mask_pos,
                                  const unsigned* __restrict__ cH,
                                  const unsigned* __restrict__ cL,
                                  unsigned* __restrict__ qH,
                                  unsigned* __restrict__ qL) {
    int i = blockIdx.x * blockDim.x + threadIdx.x;
    if (i >= MQ * KP2) return;
    int c = i & (KP2 - 1);
    int r = i / KP2;
    int b = r / NM;
    int p = mask_pos[r];
    size_t src = ((size_t)b * SC + p) * KP2 + c;
    qH[i] = cH[src];
    qL[i] = cL[src];
}

__global__ void prepack_kernel(const float* __restrict__ in,
                               unsigned* __restrict__ H,
                               unsigned* __restrict__ L,
                               long npairs, int do_tanh) {
    long i = (long)blockIdx.x * blockDim.x + threadIdx.x;
    if (i >= npairs) return;
    float2 v = ((const float2*)in)[i];
    if (do_tanh) { v.x = tanhf(v.x); v.y = tanhf(v.y); }
    split_pack(v.x, v.y, H[i], L[i]);
}

// ---------------- mma / ldmatrix / cp.async helpers ----------------------------
__device__ __forceinline__ void mma_bf16(float* c, const unsigned* a, const unsigned* b) {
    asm("mma.sync.aligned.m16n8k16.row.col.f32.bf16.bf16.f32 "
        "{%0,%1,%2,%3}, {%4,%5,%6,%7}, {%8,%9}, {%0,%1,%2,%3};"
        : "+f"(c[0]), "+f"(c[1]), "+f"(c[2]), "+f"(c[3])
        : "r"(a[0]), "r"(a[1]), "r"(a[2]), "r"(a[3]), "r"(b[0]), "r"(b[1]));
}
__device__ __forceinline__ void cp16(void* dst, const void* src, bool ok) {
    unsigned d = (unsigned)__cvta_generic_to_shared(dst);
    int sz = ok ? 16 : 0;
    asm volatile("cp.async.cg.shared.global [%0], [%1], 16, %2;"
                 :: "r"(d), "l"(src), "r"(sz));
}
#define LDSM4(r, a)                                                          \
    asm volatile("ldmatrix.sync.aligned.m8n8.x4.shared.b16 {%0,%1,%2,%3}, [%4];" \
                 : "=r"((r)[0]), "=r"((r)[1]), "=r"((r)[2]), "=r"((r)[3])    \
                 : "r"(a))

#define PITCH 20
#define TSZ (128*PITCH)

// ======== fragment-load + mma block shared by all GEMM variants ==============
#define MMA_STEP(baseAH, baseAL, baseBH, baseBL)                                 \
    _Pragma("unroll")                                                            \
    for (int ks = 0; ks < 2; ++ks) {                                             \
        int kc = ks * 8;                                                         \
        unsigned ah[4][4], al[4][4];                                             \
        _Pragma("unroll")                                                        \
        for (int mt = 0; mt < 4; ++mt) {                                         \
            uint32_t off = (uint32_t)(((a_row + mt * 16) * PITCH + kc + a_col) * 4); \
            LDSM4(ah[mt], (baseAH) + off);                                       \
            LDSM4(al[mt], (baseAL) + off);                                       \
        }                                                                        \
        unsigned bh[4][2], bl[4][2];                                             \
        _Pragma("unroll")                                                        \
        for (int np = 0; np < 2; ++np) {                                         \
            uint32_t off = (uint32_t)(((b_row + np * 16) * PITCH + kc + b_col) * 4); \
            unsigned rh[4], rl[4];                                               \
            LDSM4(rh, (baseBH) + off);                                           \
            LDSM4(rl, (baseBL) + off);                                           \
            bh[np * 2][0]     = rh[0]; bh[np * 2][1]     = rh[1];                \
            bh[np * 2 + 1][0] = rh[2]; bh[np * 2 + 1][1] = rh[3];                \
            bl[np * 2][0]     = rl[0]; bl[np * 2][1]     = rl[1];                \
            bl[np * 2 + 1][0] = rl[2]; bl[np * 2 + 1][1] = rl[3];                \
        }                                                                        \
        _Pragma("unroll")                                                        \
        for (int mt = 0; mt < 4; ++mt)                                           \
            _Pragma("unroll")                                                    \
            for (int nt = 0; nt < 4; ++nt) {                                     \
                mma_bf16(acc[mt][nt], ah[mt], bh[nt]);                           \
                mma_bf16(acc[mt][nt], al[mt], bh[nt]);                           \
                mma_bf16(acc[mt][nt], ah[mt], bl[nt]);                           \
            }                                                                    \
    }

#define GEMM_PROLOG()                                                            \
    int bm = blockIdx.x * 128;                                                   \
    int bn = blockIdx.y * 128;                                                   \
    int tid = threadIdx.x;                                                       \
    int wid = tid >> 5;                                                          \
    int lane = tid & 31;                                                         \
    int warp_m = wid >> 2;                                                       \
    int warp_n = wid & 3;                                                        \
    int g  = lane >> 2;                                                          \
    int tg = lane & 3;                                                           \
    int m_base = warp_m * 64;                                                    \
    int n_base = warp_n * 32;                                                    \
    int a_row = m_base + (lane & 15);                                            \
    int a_col = (lane >> 4) * 4;                                                 \
    int b_row = n_base + ((lane >> 4) & 1) * 8 + (lane & 7);                     \
    int b_col = ((lane >> 3) & 1) * 4;                                           \
    float acc[4][4][4];                                                          \
    _Pragma("unroll")                                                            \
    for (int mt = 0; mt < 4; ++mt)                                               \
        _Pragma("unroll")                                                        \
        for (int nt = 0; nt < 4; ++nt)                                           \
            _Pragma("unroll")                                                    \
            for (int i = 0; i < 4; ++i) acc[mt][nt][i] = 0.f;                    \
    int srow0 = tid >> 2;                                                        \
    int sc4   = (tid & 3) * 4;                                                   \
    int srow1 = (tid + 256) >> 2;

#define STAGE_PK(buf, k0p)                                                       \
    {                                                                            \
        unsigned* bAH = sm + (buf) * 4 * TSZ;                                    \
        unsigned* bAL = bAH + TSZ;                                               \
        unsigned* bBH = bAH + 2 * TSZ;                                           \
        unsigned* bBL = bAH + 3 * TSZ;                                           \
        _Pragma("unroll")                                                        \
        for (int i = 0; i < 2; ++i) {                                            \
            int row = i ? srow1 : srow0;                                         \
            cp16(bAH + row * PITCH + sc4, AH + (size_t)(bm + row) * KP2 + (k0p) + sc4, true); \
            cp16(bAL + row * PITCH + sc4, AL + (size_t)(bm + row) * KP2 + (k0p) + sc4, true); \
            int nrow = bn + row;                                                 \
            bool ok = nrow < N;                                                  \
            size_t bro = (size_t)(ok ? nrow : 0) * KP2 + (k0p) + sc4;            \
            cp16(bBH + row * PITCH + sc4, BH + bro, ok);                         \
            cp16(bBL + row * PITCH + sc4, BL + bro, ok);                         \
        }                                                                        \
        asm volatile("cp.async.commit_group;");                                  \
    }

#define GEMM_MAINLOOP()                                                          \
    STAGE_PK(0, 0);                                                              \
    const int NSTEP = DM / 32;                                                   \
    for (int s = 0; s < NSTEP; ++s) {                                            \
        if (s + 1 < NSTEP) {                                                     \
            STAGE_PK((s + 1) & 1, (s + 1) * 16);                                 \
            asm volatile("cp.async.wait_group 1;");                              \
        } else {                                                                 \
            asm volatile("cp.async.wait_group 0;");                              \
        }                                                                        \
        __syncthreads();                                                         \
        uint32_t baseAH = smem_u32 + ((s & 1) * 4 * TSZ) * 4;                    \
        MMA_STEP(baseAH, baseAH + TSZ * 4, baseAH + 2 * TSZ * 4, baseAH + 3 * TSZ * 4); \
        __syncthreads();                                                         \
    }

// ---------------- GEMM variant 1: packed A/B, f32 C + bias --------------------
__global__ __launch_bounds__(256)
void gemm_pk_kernel(const unsigned* __restrict__ AH, const unsigned* __restrict__ AL,
                    const unsigned* __restrict__ BH, const unsigned* __restrict__ BL,
                    const float* __restrict__ bias,
                    float* __restrict__ C,
                    int M, int N, int ldc) {
    extern __shared__ unsigned sm[];
    uint32_t smem_u32 = (uint32_t)__cvta_generic_to_shared(sm);
    GEMM_PROLOG();
    GEMM_MAINLOOP();

#pragma unroll
    for (int mt = 0; mt < 4; ++mt) {
        int row0 = bm + m_base + mt * 16 + g;
#pragma unroll
        for (int nt = 0; nt < 4; ++nt) {
            int col0 = bn + n_base + nt * 8 + 2 * tg;
            float b0 = bias ? bias[col0] : 0.f;
            float b1 = bias ? bias[col0 + 1] : 0.f;
            C[(size_t)row0 * ldc + col0]           = acc[mt][nt][0] + b0;
            C[(size_t)row0 * ldc + col0 + 1]       = acc[mt][nt][1] + b1;
            C[(size_t)(row0 + 8) * ldc + col0]     = acc[mt][nt][2] + b0;
            C[(size_t)(row0 + 8) * ldc + col0 + 1] = acc[mt][nt][3] + b1;
        }
    }
}

// ---------------- GEMM variant 2: packed A/B, packed-out C (for t2) -----------
__global__ __launch_bounds__(256)
void gemm_pk_packout_kernel(const unsigned* __restrict__ AH, const unsigned* __restrict__ AL,
                            const unsigned* __restrict__ BH, const unsigned* __restrict__ BL,
                            const float* __restrict__ bias,
                            unsigned* __restrict__ CH, unsigned* __restrict__ CL,
                            int M, int N) {
    extern __shared__ unsigned sm[];
    uint32_t smem_u32 = (uint32_t)__cvta_generic_to_shared(sm);
    GEMM_PROLOG();
    GEMM_MAINLOOP();

#pragma unroll
    for (int mt = 0; mt < 4; ++mt) {
        int row0 = bm + m_base + mt * 16 + g;
#pragma unroll
        for (int nt = 0; nt < 4; ++nt) {
            int col0 = bn + n_base + nt * 8 + 2 * tg;
            float b0 = bias[col0], b1 = bias[col0 + 1];
            float v0 = acc[mt][nt][0] + b0, v1 = acc[mt][nt][1] + b1;
            float v2 = acc[mt][nt][2] + b0, v3 = acc[mt][nt][3] + b1;
            size_t p0 = (size_t)row0 * KP2 + (col0 >> 1);
            size_t p1 = (size_t)(row0 + 8) * KP2 + (col0 >> 1);
            split_pack(v0, v1, CH[p0], CL[p0]);
            split_pack(v2, v3, CH[p1], CL[p1]);
        }
    }
}

// ---------------- GEMM variant 3: packed A/B, C + LSE partials (scores) --------
__global__ __launch_bounds__(256)
void gemm_pk_score_kernel(const unsigned* __restrict__ AH, const unsigned* __restrict__ AL,
                          const unsigned* __restrict__ BH, const unsigned* __restrict__ BL,
                          float* __restrict__ C,
                          float2* __restrict__ part,
                          int N) {
    extern __shared__ unsigned sm[];
    uint32_t smem_u32 = (uint32_t)__cvta_generic_to_shared(sm);
    GEMM_PROLOG();
    GEMM_MAINLOOP();

    // epilogue: store C + per-row (max, sumexp) partials, reduced in smem
    float2* red = (float2*)sm;     // [128][16] = 16 KB, staging buffer reuse
#pragma unroll
    for (int mt = 0; mt < 4; ++mt) {
        int rl0 = m_base + mt * 16 + g;
        int row0 = bm + rl0;
        float m0 = -INFINITY, s0 = 0.f, m1 = -INFINITY, s1 = 0.f;
#pragma unroll
        for (int nt = 0; nt < 4; ++nt) {
            int col0 = bn + n_base + nt * 8 + 2 * tg;
            float v00 = acc[mt][nt][0], v01 = acc[mt][nt][1];
            float v10 = acc[mt][nt][2], v11 = acc[mt][nt][3];
            if (col0 < N) {
                C[(size_t)row0 * N + col0]       = v00;
                C[(size_t)(row0 + 8) * N + col0] = v10;
                float nm0 = fmaxf(m0, v00); s0 = s0 * __expf(m0 - nm0) + __expf(v00 - nm0); m0 = nm0;
                float nm1 = fmaxf(m1, v10); s1 = s1 * __expf(m1 - nm1) + __expf(v10 - nm1); m1 = nm1;
            }
            if (col0 + 1 < N) {
                C[(size_t)row0 * N + col0 + 1]       = v01;
                C[(size_t)(row0 + 8) * N + col0 + 1] = v11;
                float nm0 = fmaxf(m0, v01); s0 = s0 * __expf(m0 - nm0) + __expf(v01 - nm0); m0 = nm0;
                float nm1 = fmaxf(m1, v11); s1 = s1 * __expf(m1 - nm1) + __expf(v11 - nm1); m1 = nm1;
            }
        }
        int slot = warp_n * 4 + tg;
        red[rl0 * 16 + slot]       = make_float2(m0, s0);
        red[(rl0 + 8) * 16 + slot] = make_float2(m1, s1);
    }
    __syncthreads();
    if (tid < 128) {
        float m = -INFINITY, s = 0.f;
#pragma unroll
        for (int k = 0; k < 16; ++k) {
            float2 v = red[tid * 16 + k];
            float nm = fmaxf(m, v.x);
            s = s * __expf(m - nm) + v.y * __expf(v.x - nm);
            m = nm;
        }
        part[(size_t)blockIdx.y * MQ + bm + tid] = make_float2(m, s);
    }
}

// ---------------- attention (reads merged KV, ld=1024) ------------------------
__global__ __launch_bounds__(256)
void attn_kernel(const float* __restrict__ Q,
                 const float* __restrict__ KV,
                 float* __restrict__ out) {
    int blk = blockIdx.x;
    int b = blk / HH, h = blk % HH;

    __shared__ float sQ[NM][DH];
    __shared__ float sS[NM][SC];
    __shared__ float sKV[SC][DH + 1];

    int tid = threadIdx.x;

    for (int e = tid; e < NM * DH; e += 256) {
        int m = e / DH, d0 = e % DH;
        sQ[m][d0] = Q[((size_t)b * NM + m) * DM + h * DH + d0];
    }
    for (int e = tid; e < SC * DH; e += 256) {
        int k = e / DH, d0 = e % DH;
        sKV[k][d0] = KV[((size_t)b * SC + k) * 1024 + h * DH + d0];
    }
    __syncthreads();

    for (int e = tid; e < NM * SC; e += 256) {
        int m = e / SC, k = e % SC;
        float acc = 0.f;
#pragma unroll
        for (int d0 = 0; d0 < DH; ++d0) acc += sQ[m][d0] * sKV[k][d0];
        sS[m][k] = acc;
    }
    __syncthreads();

    int w = tid >> 5, lane = tid & 31;
    for (int m = 2 * w; m < 2 * w + 2; ++m) {
        float vals[4];
        float mx = -INFINITY;
#pragma unroll
        for (int j = 0; j < 4; ++j) {
            vals[j] = sS[m][lane * 4 + j];
            mx = fmaxf(mx, vals[j]);
        }
#pragma unroll
        for (int off = 16; off; off >>= 1)
            mx = fmaxf(mx, __shfl_xor_sync(0xffffffffu, mx, off));
        float sum = 0.f;
#pragma unroll
        for (int j = 0; j < 4; ++j) {
            vals[j] = expf(vals[j] - mx);
            sum += vals[j];
        }
#pragma unroll
        for (int off = 16; off; off >>= 1)
            sum += __shfl_xor_sync(0xffffffffu, sum, off);
        float inv = 1.f / sum;
#pragma unroll
        for (int j = 0; j < 4; ++j) sS[m][lane * 4 + j] = vals[j] * inv;
    }
    __syncthreads();

    for (int e = tid; e < SC * DH; e += 256) {
        int k = e / DH, d0 = e % DH;
        sKV[k][d0] = KV[((size_t)b * SC + k) * 1024 + 512 + h * DH + d0];
    }
    __syncthreads();

    for (int e = tid; e < NM * DH; e += 256) {
        int m = e / DH, d0 = e % DH;
        float acc = 0.f;
#pragma unroll
        for (int k = 0; k < SC; ++k) acc += sS[m][k] * sKV[k][d0];
        out[((size_t)b * NM + m) * DM + h * DH + d0] = acc;
    }
}

// ---------------- LSE reduce + subtract ---------------------------------------
__global__ void lse_reduce_kernel(const float2* __restrict__ part,
                                  float* __restrict__ lse) {
    int row = blockIdx.x;
    int lane = threadIdx.x;
    float m = -INFINITY, s = 0.f;
    for (int c = lane; c < NCHUNK; c += 32) {
        float2 v = part[(size_t)c * MQ + row];
        float nm = fmaxf(m, v.x);
        s = s * __expf(m - nm) + v.y * __expf(v.x - nm);
        m = nm;
    }
#pragma unroll
    for (int off = 16; off; off >>= 1) {
        float m2 = __shfl_xor_sync(0xffffffffu, m, off);
        float s2 = __shfl_xor_sync(0xffffffffu, s, off);
        float nm = fmaxf(m, m2);
        s = s * __expf(m - nm) + s2 * __expf(m2 - nm);
        m = nm;
    }
    if (lane == 0) lse[row] = m + logf(s);
}

__global__ __launch_bounds__(256)
void subtract_kernel(float* __restrict__ out, const float* __restrict__ lse) {
    int row = blockIdx.x;
    float l = lse[row];
    float* p = out + (size_t)row * NC;
    for (int i = threadIdx.x; i < NC; i += 256) p[i] -= l;
}

// ---------------- launch -----------------------------------------------------
extern "C" void kernel_launch(void* const* d_in, const int* in_sizes, int n_in,
                              void* d_out, int out_size) {
    const int*   mask_pos  = (const int*)d_in[2];
    const int*   mask_curr = (const int*)d_in[3];
    const float* emb       = (const float*)d_in[5];
    const float* c_wq = (const float*)d_in[12];
    const float* c_bq = (const float*)d_in[13];
    const float* c_wk = (const float*)d_in[14];
    const float* c_bk = (const float*)d_in[15];
    const float* c_wv = (const float*)d_in[16];
    const float* c_bv = (const float*)d_in[17];
    const float* t2_w = (const float*)d_in[24];
    const float* t2_b = (const float*)d_in[25];
    float* out = (float*)d_out;

    float *KV, *Qb, *attn, *bKV, *lse;
    float2* part;
    cudaGetSymbolAddress((void**)&KV,   g_KV);
    cudaGetSymbolAddress((void**)&Qb,   g_Q);
    cudaGetSymbolAddress((void**)&attn, g_attn);
    cudaGetSymbolAddress((void**)&bKV,  g_bKV);
    cudaGetSymbolAddress((void**)&part, g_part);
    cudaGetSymbolAddress((void**)&lse,  g_lse);

    unsigned *embH, *embL, *currH, *currL, *wkvH, *wkvL, *wqH, *wqL, *t2H, *t2L;
    unsigned *qinH, *qinL, *tanhH, *tanhL, *hybH, *hybL;
    cudaGetSymbolAddress((void**)&embH,  g_pk_embH);
    cudaGetSymbolAddress((void**)&embL,  g_pk_embL);
    cudaGetSymbolAddress((void**)&currH, g_pk_currH);
    cudaGetSymbolAddress((void**)&currL, g_pk_currL);
    cudaGetSymbolAddress((void**)&wkvH,  g_pk_wkvH);
    cudaGetSymbolAddress((void**)&wkvL,  g_pk_wkvL);
    cudaGetSymbolAddress((void**)&wqH,   g_pk_wqH);
    cudaGetSymbolAddress((void**)&wqL,   g_pk_wqL);
    cudaGetSymbolAddress((void**)&t2H,   g_pk_t2H);
    cudaGetSymbolAddress((void**)&t2L,   g_pk_t2L);
    cudaGetSymbolAddress((void**)&qinH,  g_pk_qinH);
    cudaGetSymbolAddress((void**)&qinL,  g_pk_qinL);
    cudaGetSymbolAddress((void**)&tanhH, g_pk_tanhH);
    cudaGetSymbolAddress((void**)&tanhL, g_pk_tanhL);
    cudaGetSymbolAddress((void**)&hybH,  g_pk_hybH);
    cudaGetSymbolAddress((void**)&hybL,  g_pk_hybL);

    const int SMEMB = 2 * 4 * TSZ * 4;    // 81920 B
    cudaFuncSetAttribute(gemm_pk_kernel,
                         cudaFuncAttributeMaxDynamicSharedMemorySize, SMEMB);
    cudaFuncSetAttribute(gemm_pk_packout_kernel,
                         cudaFuncAttributeMaxDynamicSharedMemorySize, SMEMB);
    cudaFuncSetAttribute(gemm_pk_score_kernel,
                         cudaFuncAttributeMaxDynamicSharedMemorySize, SMEMB);

    const long WP = (long)DM * KP2;        // pairs per 512x512 matrix

    // 1. weight prepacks + bias concat + emb prepack
    prepack_kernel<<<(int)((WP + 255) / 256), 256>>>(c_wk, wkvH,      wkvL,      WP, 0);
    prepack_kernel<<<(int)((WP + 255) / 256), 256>>>(c_wv, wkvH + WP, wkvL + WP, WP, 0);
    prepack_kernel<<<(int)((WP + 255) / 256), 256>>>(c_wq, wqH,       wqL,       WP, 0);
    prepack_kernel<<<(int)((WP + 255) / 256), 256>>>(t2_w, t2H,       t2L,       WP, 0);
    concat_bias_kernel<<<4, 256>>>(c_bk, c_bv, bKV);
    {
        long np = (long)NC * KP2;
        prepack_kernel<<<(int)((np + 255) / 256), 256>>>(emb + 2 * DM, embH, embL, np, 0);
    }

    // 2. curr = emb[mask_curr] + PE, packed directly
    gather_pe_pack_kernel<<<(BB * SC * KP2 + 255) / 256, 256>>>(mask_curr, emb,
                                                                currH, currL);

    // 3. merged K|V projection: [4096, 1024]
    {
        dim3 g((BB * SC) / 128, 1024 / 128);
        gemm_pk_kernel<<<g, 256, SMEMB>>>(currH, currL, wkvH, wkvL, bKV, KV,
                                          BB * SC, 1024, 1024);
    }

    // 4. Q projection over the 512 gathered rows (packed gather)
    gather_qpk_kernel<<<(MQ * KP2 + 255) / 256, 256>>>(mask_pos, currH, currL, qinH, qinL);
    {
        dim3 g(MQ / 128, DM / 128);
        gemm_pk_kernel<<<g, 256, SMEMB>>>(qinH, qinL, wqH, wqL, c_bq, Qb, MQ, DM, DM);
    }

    // 5. attention
    attn_kernel<<<BB * HH, 256>>>(Qb, KV, attn);

    // 6. hyb = tanh(attn) @ t2_w^T + t2_b, emitted directly as packed hi/lo
    prepack_kernel<<<(MQ * KP2 + 255) / 256, 256>>>(attn, tanhH, tanhL, MQ * KP2, 1);
    {
        dim3 g(MQ / 128, DM / 128);
        gemm_pk_packout_kernel<<<g, 256, SMEMB>>>(tanhH, tanhL, t2H, t2L, t2_b,
                                                  hybH, hybL, MQ, DM);
    }

    // 7. scores = hyb @ emb[2:]^T with fused LSE partials
    {
        dim3 g(MQ / 128, NCHUNK);
        gemm_pk_score_kernel<<<g, 256, SMEMB>>>(hybH, hybL, embH, embL, out, part, NC);
    }

    // 8. lse reduce + subtract
    lse_reduce_kernel<<<MQ, 32>>>(part, lse);
    subtract_kernel<<<MQ, 256>>>(out, lse);
}

// round 9
// speedup vs baseline: 1.1663x; 1.1141x over previous
#include <cuda_runtime.h>
#include <cuda_bf16.h>
#include <math.h>
#include <stdint.h>

#define BB 32
#define SC 128
#define NM 16
#define DM 512
#define HH 8
#define DH 64
#define NC 39998
#define MQ (BB*NM)    /* 512 gathered query rows */
#define KP2 256       /* packed pairs per row (DM/2) */
#define NCHUNK 313    /* ceil(NC/128) */

// ---------------- scratch (device globals; no allocation allowed) -------------
__device__ float g_KV[BB*SC*1024];     // K cols 0..511, V cols 512..1023
__device__ float g_Q[MQ*DM];
__device__ float g_attn[MQ*DM];
__device__ float g_bKV[1024];
__device__ float2 g_part[NCHUNK*MQ];   // per (chunk,row) partial (max, sumexp)
__device__ float g_lse[MQ];

// packed bf16 hi/lo operands
__device__ unsigned g_pk_embH[(size_t)NC*KP2];
__device__ unsigned g_pk_embL[(size_t)NC*KP2];
__device__ unsigned g_pk_currH[BB*SC*KP2];
__device__ unsigned g_pk_currL[BB*SC*KP2];
__device__ unsigned g_pk_wkvH[1024*KP2];
__device__ unsigned g_pk_wkvL[1024*KP2];
__device__ unsigned g_pk_wqH[DM*KP2];
__device__ unsigned g_pk_wqL[DM*KP2];
__device__ unsigned g_pk_t2H[DM*KP2];
__device__ unsigned g_pk_t2L[DM*KP2];
__device__ unsigned g_pk_qinH[MQ*KP2];
__device__ unsigned g_pk_qinL[MQ*KP2];
__device__ unsigned g_pk_tanhH[MQ*KP2];
__device__ unsigned g_pk_tanhL[MQ*KP2];
__device__ unsigned g_pk_hybH[MQ*KP2];
__device__ unsigned g_pk_hybL[MQ*KP2];

// ---------------- bf16 split helper ------------------------------------------
__device__ __forceinline__ void split_pack(float x, float y,
                                           unsigned& hi, unsigned& lo) {
    __nv_bfloat16 hx = __float2bfloat16_rn(x);
    __nv_bfloat16 hy = __float2bfloat16_rn(y);
    float rx = x - __bfloat162float(hx);
    float ry = y - __bfloat162float(hy);
    __nv_bfloat16 lx = __float2bfloat16_rn(rx);
    __nv_bfloat16 ly = __float2bfloat16_rn(ry);
    hi = ((unsigned)__bfloat16_as_ushort(hy) << 16) | __bfloat16_as_ushort(hx);
    lo = ((unsigned)__bfloat16_as_ushort(ly) << 16) | __bfloat16_as_ushort(lx);
}

// ---------------- small elementwise kernels -----------------------------------
__global__ void concat_bias_kernel(const float* __restrict__ bk,
                                   const float* __restrict__ bv,
                                   float* __restrict__ out) {
    int t = blockIdx.x * blockDim.x + threadIdx.x;
    if (t < 512) out[t] = bk[t];
    else if (t < 1024) out[t] = bv[t - 512];
}

// gather + positional embedding; emits packed hi/lo directly
__global__ void gather_pe_pack_kernel(const int* __restrict__ idx,
                                      const float* __restrict__ emb,
                                      unsigned* __restrict__ H,
                                      unsigned* __restrict__ L) {
    int i = blockIdx.x * blockDim.x + threadIdx.x;     // pair index
    if (i >= BB * SC * KP2) return;
    int pp  = i & (KP2 - 1);
    int row = i / KP2;
    int s   = row & (SC - 1);
    int g   = idx[row];
    int d0  = pp * 2;
    float freq = expf((float)d0 * -0.0179889460176f);  // -ln(10000)/512
    float ang  = (float)s * freq;
    float v0 = emb[(size_t)g * DM + d0]     + sinf(ang);
    float v1 = emb[(size_t)g * DM + d0 + 1] + cosf(ang);
    split_pack(v0, v1, H[i], L[i]);
}

// gather packed rows of curr at mask positions
__global__ void gather_qpk_kernel(const int* __restrict__ mask_pos,
                                  const unsigned* __restrict__ cH,
                                  const unsigned* __restrict__ cL,
                                  unsigned* __restrict__ qH,
                                  unsigned* __restrict__ qL) {
    int i = blockIdx.x * blockDim.x + threadIdx.x;
    if (i >= MQ * KP2) return;
    int c = i & (KP2 - 1);
    int r = i / KP2;
    int b = r / NM;
    int p = mask_pos[r];
    size_t src = ((size_t)b * SC + p) * KP2 + c;
    qH[i] = cH[src];
    qL[i] = cL[src];
}

__global__ void prepack_kernel(const float* __restrict__ in,
                               unsigned* __restrict__ H,
                               unsigned* __restrict__ L,
                               long npairs, int do_tanh) {
    long i = (long)blockIdx.x * blockDim.x + threadIdx.x;
    if (i >= npairs) return;
    float2 v = ((const float2*)in)[i];
    if (do_tanh) { v.x = tanhf(v.x); v.y = tanhf(v.y); }
    split_pack(v.x, v.y, H[i], L[i]);
}

// ---------------- mma / ldmatrix / cp.async helpers ----------------------------
__device__ __forceinline__ void mma_bf16(float* c, const unsigned* a, const unsigned* b) {
    asm("mma.sync.aligned.m16n8k16.row.col.f32.bf16.bf16.f32 "
        "{%0,%1,%2,%3}, {%4,%5,%6,%7}, {%8,%9}, {%0,%1,%2,%3};"
        : "+f"(c[0]), "+f"(c[1]), "+f"(c[2]), "+f"(c[3])
        : "r"(a[0]), "r"(a[1]), "r"(a[2]), "r"(a[3]), "r"(b[0]), "r"(b[1]));
}
__device__ __forceinline__ void cp16(void* dst, const void* src, bool ok) {
    unsigned d = (unsigned)__cvta_generic_to_shared(dst);
    int sz = ok ? 16 : 0;
    asm volatile("cp.async.cg.shared.global [%0], [%1], 16, %2;"
                 :: "r"(d), "l"(src), "r"(sz));
}
#define LDSM4(r, a)                                                          \
    asm volatile("ldmatrix.sync.aligned.m8n8.x4.shared.b16 {%0,%1,%2,%3}, [%4];" \
                 : "=r"((r)[0]), "=r"((r)[1]), "=r"((r)[2]), "=r"((r)[3])    \
                 : "r"(a))

#define PITCH 20
#define TSZ (128*PITCH)

// ======== fragment-load + mma block shared by all GEMM variants ==============
// Three product passes (hh, lh, hl): consecutive HMMAs hit independent acc
// tiles (16-deep ILP); per-tile accumulation order unchanged => bit-identical.
#define MMA_STEP(baseAH, baseAL, baseBH, baseBL)                                 \
    _Pragma("unroll")                                                            \
    for (int ks = 0; ks < 2; ++ks) {                                             \
        int kc = ks * 8;                                                         \
        unsigned ah[4][4], al[4][4];                                             \
        _Pragma("unroll")                                                        \
        for (int mt = 0; mt < 4; ++mt) {                                         \
            uint32_t off = (uint32_t)(((a_row + mt * 16) * PITCH + kc + a_col) * 4); \
            LDSM4(ah[mt], (baseAH) + off);                                       \
            LDSM4(al[mt], (baseAL) + off);                                       \
        }                                                                        \
        unsigned bh[4][2], bl[4][2];                                             \
        _Pragma("unroll")                                                        \
        for (int np = 0; np < 2; ++np) {                                         \
            uint32_t off = (uint32_t)(((b_row + np * 16) * PITCH + kc + b_col) * 4); \
            unsigned rh[4], rl[4];                                               \
            LDSM4(rh, (baseBH) + off);                                           \
            LDSM4(rl, (baseBL) + off);                                           \
            bh[np * 2][0]     = rh[0]; bh[np * 2][1]     = rh[1];                \
            bh[np * 2 + 1][0] = rh[2]; bh[np * 2 + 1][1] = rh[3];                \
            bl[np * 2][0]     = rl[0]; bl[np * 2][1]     = rl[1];                \
            bl[np * 2 + 1][0] = rl[2]; bl[np * 2 + 1][1] = rl[3];                \
        }                                                                        \
        _Pragma("unroll")                                                        \
        for (int mt = 0; mt < 4; ++mt)                                           \
            _Pragma("unroll")                                                    \
            for (int nt = 0; nt < 4; ++nt)                                       \
                mma_bf16(acc[mt][nt], ah[mt], bh[nt]);                           \
        _Pragma("unroll")                                                        \
        for (int mt = 0; mt < 4; ++mt)                                           \
            _Pragma("unroll")                                                    \
            for (int nt = 0; nt < 4; ++nt)                                       \
                mma_bf16(acc[mt][nt], al[mt], bh[nt]);                           \
        _Pragma("unroll")                                                        \
        for (int mt = 0; mt < 4; ++mt)                                           \
            _Pragma("unroll")                                                    \
            for (int nt = 0; nt < 4; ++nt)                                       \
                mma_bf16(acc[mt][nt], ah[mt], bl[nt]);                           \
    }

#define GEMM_PROLOG()                                                            \
    int bm = blockIdx.x * 128;                                                   \
    int bn = blockIdx.y * 128;                                                   \
    int tid = threadIdx.x;                                                       \
    int wid = tid >> 5;                                                          \
    int lane = tid & 31;                                                         \
    int warp_m = wid >> 2;                                                       \
    int warp_n = wid & 3;                                                        \
    int g  = lane >> 2;                                                          \
    int tg = lane & 3;                                                           \
    int m_base = warp_m * 64;                                                    \
    int n_base = warp_n * 32;                                                    \
    int a_row = m_base + (lane & 15);                                            \
    int a_col = (lane >> 4) * 4;                                                 \
    int b_row = n_base + ((lane >> 4) & 1) * 8 + (lane & 7);                     \
    int b_col = ((lane >> 3) & 1) * 4;                                           \
    float acc[4][4][4];                                                          \
    _Pragma("unroll")                                                            \
    for (int mt = 0; mt < 4; ++mt)                                               \
        _Pragma("unroll")                                                        \
        for (int nt = 0; nt < 4; ++nt)                                           \
            _Pragma("unroll")                                                    \
            for (int i = 0; i < 4; ++i) acc[mt][nt][i] = 0.f;                    \
    int srow0 = tid >> 2;                                                        \
    int sc4   = (tid & 3) * 4;                                                   \
    int srow1 = (tid + 256) >> 2;

#define STAGE_PK(buf, k0p)                                                       \
    {                                                                            \
        unsigned* bAH = sm + (buf) * 4 * TSZ;                                    \
        unsigned* bAL = bAH + TSZ;                                               \
        unsigned* bBH = bAH + 2 * TSZ;                                           \
        unsigned* bBL = bAH + 3 * TSZ;                                           \
        _Pragma("unroll")                                                        \
        for (int i = 0; i < 2; ++i) {                                            \
            int row = i ? srow1 : srow0;                                         \
            cp16(bAH + row * PITCH + sc4, AH + (size_t)(bm + row) * KP2 + (k0p) + sc4, true); \
            cp16(bAL + row * PITCH + sc4, AL + (size_t)(bm + row) * KP2 + (k0p) + sc4, true); \
            int nrow = bn + row;                                                 \
            bool ok = nrow < N;                                                  \
            size_t bro = (size_t)(ok ? nrow : 0) * KP2 + (k0p) + sc4;            \
            cp16(bBH + row * PITCH + sc4, BH + bro, ok);                         \
            cp16(bBL + row * PITCH + sc4, BL + bro, ok);                         \
        }                                                                        \
        asm volatile("cp.async.commit_group;");                                  \
    }

#define GEMM_MAINLOOP()                                                          \
    STAGE_PK(0, 0);                                                              \
    const int NSTEP = DM / 32;                                                   \
    for (int s = 0; s < NSTEP; ++s) {                                            \
        if (s + 1 < NSTEP) {                                                     \
            STAGE_PK((s + 1) & 1, (s + 1) * 16);                                 \
            asm volatile("cp.async.wait_group 1;");                              \
        } else {                                                                 \
            asm volatile("cp.async.wait_group 0;");                              \
        }                                                                        \
        __syncthreads();                                                         \
        uint32_t baseAH = smem_u32 + ((s & 1) * 4 * TSZ) * 4;                    \
        MMA_STEP(baseAH, baseAH + TSZ * 4, baseAH + 2 * TSZ * 4, baseAH + 3 * TSZ * 4); \
        __syncthreads();                                                         \
    }

// ---------------- GEMM variant 1: packed A/B, f32 C + bias --------------------
__global__ __launch_bounds__(256, 2)
void gemm_pk_kernel(const unsigned* __restrict__ AH, const unsigned* __restrict__ AL,
                    const unsigned* __restrict__ BH, const unsigned* __restrict__ BL,
                    const float* __restrict__ bias,
                    float* __restrict__ C,
                    int M, int N, int ldc) {
    extern __shared__ unsigned sm[];
    uint32_t smem_u32 = (uint32_t)__cvta_generic_to_shared(sm);
    GEMM_PROLOG();
    GEMM_MAINLOOP();

#pragma unroll
    for (int mt = 0; mt < 4; ++mt) {
        int row0 = bm + m_base + mt * 16 + g;
#pragma unroll
        for (int nt = 0; nt < 4; ++nt) {
            int col0 = bn + n_base + nt * 8 + 2 * tg;
            float b0 = bias ? bias[col0] : 0.f;
            float b1 = bias ? bias[col0 + 1] : 0.f;
            C[(size_t)row0 * ldc + col0]           = acc[mt][nt][0] + b0;
            C[(size_t)row0 * ldc + col0 + 1]       = acc[mt][nt][1] + b1;
            C[(size_t)(row0 + 8) * ldc + col0]     = acc[mt][nt][2] + b0;
            C[(size_t)(row0 + 8) * ldc + col0 + 1] = acc[mt][nt][3] + b1;
        }
    }
}

// ---------------- GEMM variant 2: packed A/B, packed-out C (for t2) -----------
__global__ __launch_bounds__(256, 2)
void gemm_pk_packout_kernel(const unsigned* __restrict__ AH, const unsigned* __restrict__ AL,
                            const unsigned* __restrict__ BH, const unsigned* __restrict__ BL,
                            const float* __restrict__ bias,
                            unsigned* __restrict__ CH, unsigned* __restrict__ CL,
                            int M, int N) {
    extern __shared__ unsigned sm[];
    uint32_t smem_u32 = (uint32_t)__cvta_generic_to_shared(sm);
    GEMM_PROLOG();
    GEMM_MAINLOOP();

#pragma unroll
    for (int mt = 0; mt < 4; ++mt) {
        int row0 = bm + m_base + mt * 16 + g;
#pragma unroll
        for (int nt = 0; nt < 4; ++nt) {
            int col0 = bn + n_base + nt * 8 + 2 * tg;
            float b0 = bias[col0], b1 = bias[col0 + 1];
            float v0 = acc[mt][nt][0] + b0, v1 = acc[mt][nt][1] + b1;
            float v2 = acc[mt][nt][2] + b0, v3 = acc[mt][nt][3] + b1;
            size_t p0 = (size_t)row0 * KP2 + (col0 >> 1);
            size_t p1 = (size_t)(row0 + 8) * KP2 + (col0 >> 1);
            split_pack(v0, v1, CH[p0], CL[p0]);
            split_pack(v2, v3, CH[p1], CL[p1]);
        }
    }
}

// ---------------- GEMM variant 3: packed A/B, C + LSE partials (scores) --------
__global__ __launch_bounds__(256, 2)
void gemm_pk_score_kernel(const unsigned* __restrict__ AH, const unsigned* __restrict__ AL,
                          const unsigned* __restrict__ BH, const unsigned* __restrict__ BL,
                          float* __restrict__ C,
                          float2* __restrict__ part,
                          int N) {
    extern __shared__ unsigned sm[];
    uint32_t smem_u32 = (uint32_t)__cvta_generic_to_shared(sm);
    GEMM_PROLOG();
    GEMM_MAINLOOP();

    // epilogue: store C + per-row (max, sumexp) partials, reduced in smem
    float2* red = (float2*)sm;     // [128][16] = 16 KB, staging buffer reuse
#pragma unroll
    for (int mt = 0; mt < 4; ++mt) {
        int rl0 = m_base + mt * 16 + g;
        int row0 = bm + rl0;
        float m0 = -INFINITY, s0 = 0.f, m1 = -INFINITY, s1 = 0.f;
#pragma unroll
        for (int nt = 0; nt < 4; ++nt) {
            int col0 = bn + n_base + nt * 8 + 2 * tg;
            float v00 = acc[mt][nt][0], v01 = acc[mt][nt][1];
            float v10 = acc[mt][nt][2], v11 = acc[mt][nt][3];
            if (col0 < N) {
                C[(size_t)row0 * N + col0]       = v00;
                C[(size_t)(row0 + 8) * N + col0] = v10;
                float nm0 = fmaxf(m0, v00); s0 = s0 * __expf(m0 - nm0) + __expf(v00 - nm0); m0 = nm0;
                float nm1 = fmaxf(m1, v10); s1 = s1 * __expf(m1 - nm1) + __expf(v10 - nm1); m1 = nm1;
            }
            if (col0 + 1 < N) {
                C[(size_t)row0 * N + col0 + 1]       = v01;
                C[(size_t)(row0 + 8) * N + col0 + 1] = v11;
                float nm0 = fmaxf(m0, v01); s0 = s0 * __expf(m0 - nm0) + __expf(v01 - nm0); m0 = nm0;
                float nm1 = fmaxf(m1, v11); s1 = s1 * __expf(m1 - nm1) + __expf(v11 - nm1); m1 = nm1;
            }
        }
        int slot = warp_n * 4 + tg;
        red[rl0 * 16 + slot]       = make_float2(m0, s0);
        red[(rl0 + 8) * 16 + slot] = make_float2(m1, s1);
    }
    __syncthreads();
    if (tid < 128) {
        float m = -INFINITY, s = 0.f;
#pragma unroll
        for (int k = 0; k < 16; ++k) {
            float2 v = red[tid * 16 + k];
            float nm = fmaxf(m, v.x);
            s = s * __expf(m - nm) + v.y * __expf(v.x - nm);
            m = nm;
        }
        part[(size_t)blockIdx.y * MQ + bm + tid] = make_float2(m, s);
    }
}

// ---------------- attention (reads merged KV, ld=1024) ------------------------
__global__ __launch_bounds__(256)
void attn_kernel(const float* __restrict__ Q,
                 const float* __restrict__ KV,
                 float* __restrict__ out) {
    int blk = blockIdx.x;
    int b = blk / HH, h = blk % HH;

    __shared__ float sQ[NM][DH];
    __shared__ float sS[NM][SC];
    __shared__ float sKV[SC][DH + 1];

    int tid = threadIdx.x;

    for (int e = tid; e < NM * DH; e += 256) {
        int m = e / DH, d0 = e % DH;
        sQ[m][d0] = Q[((size_t)b * NM + m) * DM + h * DH + d0];
    }
    for (int e = tid; e < SC * DH; e += 256) {
        int k = e / DH, d0 = e % DH;
        sKV[k][d0] = KV[((size_t)b * SC + k) * 1024 + h * DH + d0];
    }
    __syncthreads();

    for (int e = tid; e < NM * SC; e += 256) {
        int m = e / SC, k = e % SC;
        float acc = 0.f;
#pragma unroll
        for (int d0 = 0; d0 < DH; ++d0) acc += sQ[m][d0] * sKV[k][d0];
        sS[m][k] = acc;
    }
    __syncthreads();

    int w = tid >> 5, lane = tid & 31;
    for (int m = 2 * w; m < 2 * w + 2; ++m) {
        float vals[4];
        float mx = -INFINITY;
#pragma unroll
        for (int j = 0; j < 4; ++j) {
            vals[j] = sS[m][lane * 4 + j];
            mx = fmaxf(mx, vals[j]);
        }
#pragma unroll
        for (int off = 16; off; off >>= 1)
            mx = fmaxf(mx, __shfl_xor_sync(0xffffffffu, mx, off));
        float sum = 0.f;
#pragma unroll
        for (int j = 0; j < 4; ++j) {
            vals[j] = expf(vals[j] - mx);
            sum += vals[j];
        }
#pragma unroll
        for (int off = 16; off; off >>= 1)
            sum += __shfl_xor_sync(0xffffffffu, sum, off);
        float inv = 1.f / sum;
#pragma unroll
        for (int j = 0; j < 4; ++j) sS[m][lane * 4 + j] = vals[j] * inv;
    }
    __syncthreads();

    for (int e = tid; e < SC * DH; e += 256) {
        int k = e / DH, d0 = e % DH;
        sKV[k][d0] = KV[((size_t)b * SC + k) * 1024 + 512 + h * DH + d0];
    }
    __syncthreads();

    for (int e = tid; e < NM * DH; e += 256) {
        int m = e / DH, d0 = e % DH;
        float acc = 0.f;
#pragma unroll
        for (int k = 0; k < SC; ++k) acc += sS[m][k] * sKV[k][d0];
        out[((size_t)b * NM + m) * DM + h * DH + d0] = acc;
    }
}

// ---------------- LSE reduce + subtract ---------------------------------------
__global__ void lse_reduce_kernel(const float2* __restrict__ part,
                                  float* __restrict__ lse) {
    int row = blockIdx.x;
    int lane = threadIdx.x;
    float m = -INFINITY, s = 0.f;
    for (int c = lane; c < NCHUNK; c += 32) {
        float2 v = part[(size_t)c * MQ + row];
        float nm = fmaxf(m, v.x);
        s = s * __expf(m - nm) + v.y * __expf(v.x - nm);
        m = nm;
    }
#pragma unroll
    for (int off = 16; off; off >>= 1) {
        float m2 = __shfl_xor_sync(0xffffffffu, m, off);
        float s2 = __shfl_xor_sync(0xffffffffu, s, off);
        float nm = fmaxf(m, m2);
        s = s * __expf(m - nm) + s2 * __expf(m2 - nm);
        m = nm;
    }
    if (lane == 0) lse[row] = m + logf(s);
}

__global__ __launch_bounds__(256)
void subtract_kernel(float* __restrict__ out, const float* __restrict__ lse) {
    int row = blockIdx.x;
    float l = lse[row];
    float* p = out + (size_t)row * NC;
    for (int i = threadIdx.x; i < NC; i += 256) p[i] -= l;
}

// ---------------- launch -----------------------------------------------------
extern "C" void kernel_launch(void* const* d_in, const int* in_sizes, int n_in,
                              void* d_out, int out_size) {
    const int*   mask_pos  = (const int*)d_in[2];
    const int*   mask_curr = (const int*)d_in[3];
    const float* emb       = (const float*)d_in[5];
    const float* c_wq = (const float*)d_in[12];
    const float* c_bq = (const float*)d_in[13];
    const float* c_wk = (const float*)d_in[14];
    const float* c_bk = (const float*)d_in[15];
    const float* c_wv = (const float*)d_in[16];
    const float* c_bv = (const float*)d_in[17];
    const float* t2_w = (const float*)d_in[24];
    const float* t2_b = (const float*)d_in[25];
    float* out = (float*)d_out;

    float *KV, *Qb, *attn, *bKV, *lse;
    float2* part;
    cudaGetSymbolAddress((void**)&KV,   g_KV);
    cudaGetSymbolAddress((void**)&Qb,   g_Q);
    cudaGetSymbolAddress((void**)&attn, g_attn);
    cudaGetSymbolAddress((void**)&bKV,  g_bKV);
    cudaGetSymbolAddress((void**)&part, g_part);
    cudaGetSymbolAddress((void**)&lse,  g_lse);

    unsigned *embH, *embL, *currH, *currL, *wkvH, *wkvL, *wqH, *wqL, *t2H, *t2L;
    unsigned *qinH, *qinL, *tanhH, *tanhL, *hybH, *hybL;
    cudaGetSymbolAddress((void**)&embH,  g_pk_embH);
    cudaGetSymbolAddress((void**)&embL,  g_pk_embL);
    cudaGetSymbolAddress((void**)&currH, g_pk_currH);
    cudaGetSymbolAddress((void**)&currL, g_pk_currL);
    cudaGetSymbolAddress((void**)&wkvH,  g_pk_wkvH);
    cudaGetSymbolAddress((void**)&wkvL,  g_pk_wkvL);
    cudaGetSymbolAddress((void**)&wqH,   g_pk_wqH);
    cudaGetSymbolAddress((void**)&wqL,   g_pk_wqL);
    cudaGetSymbolAddress((void**)&t2H,   g_pk_t2H);
    cudaGetSymbolAddress((void**)&t2L,   g_pk_t2L);
    cudaGetSymbolAddress((void**)&qinH,  g_pk_qinH);
    cudaGetSymbolAddress((void**)&qinL,  g_pk_qinL);
    cudaGetSymbolAddress((void**)&tanhH, g_pk_tanhH);
    cudaGetSymbolAddress((void**)&tanhL, g_pk_tanhL);
    cudaGetSymbolAddress((void**)&hybH,  g_pk_hybH);
    cudaGetSymbolAddress((void**)&hybL,  g_pk_hybL);

    const int SMEMB = 2 * 4 * TSZ * 4;    // 81920 B
    cudaFuncSetAttribute(gemm_pk_kernel,
                         cudaFuncAttributeMaxDynamicSharedMemorySize, SMEMB);
    cudaFuncSetAttribute(gemm_pk_packout_kernel,
                         cudaFuncAttributeMaxDynamicSharedMemorySize, SMEMB);
    cudaFuncSetAttribute(gemm_pk_score_kernel,
                         cudaFuncAttributeMaxDynamicSharedMemorySize, SMEMB);

    const long WP = (long)DM * KP2;        // pairs per 512x512 matrix

    // 1. weight prepacks + bias concat + emb prepack
    prepack_kernel<<<(int)((WP + 255) / 256), 256>>>(c_wk, wkvH,      wkvL,      WP, 0);
    prepack_kernel<<<(int)((WP + 255) / 256), 256>>>(c_wv, wkvH + WP, wkvL + WP, WP, 0);
    prepack_kernel<<<(int)((WP + 255) / 256), 256>>>(c_wq, wqH,       wqL,       WP, 0);
    prepack_kernel<<<(int)((WP + 255) / 256), 256>>>(t2_w, t2H,       t2L,       WP, 0);
    concat_bias_kernel<<<4, 256>>>(c_bk, c_bv, bKV);
    {
        long np = (long)NC * KP2;
        prepack_kernel<<<(int)((np + 255) / 256), 256>>>(emb + 2 * DM, embH, embL, np, 0);
    }

    // 2. curr = emb[mask_curr] + PE, packed directly
    gather_pe_pack_kernel<<<(BB * SC * KP2 + 255) / 256, 256>>>(mask_curr, emb,
                                                                currH, currL);

    // 3. merged K|V projection: [4096, 1024]
    {
        dim3 g((BB * SC) / 128, 1024 / 128);
        gemm_pk_kernel<<<g, 256, SMEMB>>>(currH, currL, wkvH, wkvL, bKV, KV,
                                          BB * SC, 1024, 1024);
    }

    // 4. Q projection over the 512 gathered rows (packed gather)
    gather_qpk_kernel<<<(MQ * KP2 + 255) / 256, 256>>>(mask_pos, currH, currL, qinH, qinL);
    {
        dim3 g(MQ / 128, DM / 128);
        gemm_pk_kernel<<<g, 256, SMEMB>>>(qinH, qinL, wqH, wqL, c_bq, Qb, MQ, DM, DM);
    }

    // 5. attention
    attn_kernel<<<BB * HH, 256>>>(Qb, KV, attn);

    // 6. hyb = tanh(attn) @ t2_w^T + t2_b, emitted directly as packed hi/lo
    prepack_kernel<<<(MQ * KP2 + 255) / 256, 256>>>(attn, tanhH, tanhL, MQ * KP2, 1);
    {
        dim3 g(MQ / 128, DM / 128);
        gemm_pk_packout_kernel<<<g, 256, SMEMB>>>(tanhH, tanhL, t2H, t2L, t2_b,
                                                  hybH, hybL, MQ, DM);
    }

    // 7. scores = hyb @ emb[2:]^T with fused LSE partials
    {
        dim3 g(MQ / 128, NCHUNK);
        gemm_pk_score_kernel<<<g, 256, SMEMB>>>(hybH, hybL, embH, embL, out, part, NC);
    }

    // 8. lse reduce + subtract
    lse_reduce_kernel<<<MQ, 32>>>(part, lse);
    subtract_kernel<<<MQ, 256>>>(out, lse);
}

// round 11
// speedup vs baseline: 1.1834x; 1.0147x over previous
#include <cuda_runtime.h>
#include <cuda_bf16.h>
#include <math.h>
#include <stdint.h>

#define BB 32
#define SC 128
#define NM 16
#define DM 512
#define HH 8
#define DH 64
#define NC 39998
#define MQ (BB*NM)    /* 512 gathered query rows */
#define KP2 256       /* packed pairs per row (DM/2) */
#define NCHUNK 313    /* ceil(NC/128) */

// ---------------- scratch (device globals; no allocation allowed) -------------
__device__ float g_KV[BB*SC*1024];     // K cols 0..511, V cols 512..1023
__device__ float g_Q[MQ*DM];
__device__ float g_attn[MQ*DM];
__device__ float g_bKV[1024];
__device__ float2 g_part[NCHUNK*MQ];   // per (chunk,row) partial (max, sumexp)
__device__ float g_lse[MQ];

// packed bf16 hi/lo operands
__device__ unsigned g_pk_embH[(size_t)NC*KP2];
__device__ unsigned g_pk_embL[(size_t)NC*KP2];
__device__ unsigned g_pk_currH[BB*SC*KP2];
__device__ unsigned g_pk_currL[BB*SC*KP2];
__device__ unsigned g_pk_wkvH[1024*KP2];
__device__ unsigned g_pk_wkvL[1024*KP2];
__device__ unsigned g_pk_wqH[DM*KP2];
__device__ unsigned g_pk_wqL[DM*KP2];
__device__ unsigned g_pk_t2H[DM*KP2];
__device__ unsigned g_pk_t2L[DM*KP2];
__device__ unsigned g_pk_tanhH[MQ*KP2];
__device__ unsigned g_pk_tanhL[MQ*KP2];
__device__ unsigned g_pk_hybH[MQ*KP2];
__device__ unsigned g_pk_hybL[MQ*KP2];

// ---------------- bf16 split helper ------------------------------------------
__device__ __forceinline__ void split_pack(float x, float y,
                                           unsigned& hi, unsigned& lo) {
    __nv_bfloat16 hx = __float2bfloat16_rn(x);
    __nv_bfloat16 hy = __float2bfloat16_rn(y);
    float rx = x - __bfloat162float(hx);
    float ry = y - __bfloat162float(hy);
    __nv_bfloat16 lx = __float2bfloat16_rn(rx);
    __nv_bfloat16 ly = __float2bfloat16_rn(ry);
    hi = ((unsigned)__bfloat16_as_ushort(hy) << 16) | __bfloat16_as_ushort(hx);
    lo = ((unsigned)__bfloat16_as_ushort(ly) << 16) | __bfloat16_as_ushort(lx);
}

// ---------------- small elementwise kernels -----------------------------------
__global__ void concat_bias_kernel(const float* __restrict__ bk,
                                   const float* __restrict__ bv,
                                   float* __restrict__ out) {
    int t = blockIdx.x * blockDim.x + threadIdx.x;
    if (t < 512) out[t] = bk[t];
    else if (t < 1024) out[t] = bv[t - 512];
}

// merged prepack of wk|wv into the contiguous wkv buffer
__global__ void prepack_kv_kernel(const float* __restrict__ wk,
                                  const float* __restrict__ wv,
                                  unsigned* __restrict__ H,
                                  unsigned* __restrict__ L,
                                  long wp) {
    long i = (long)blockIdx.x * blockDim.x + threadIdx.x;
    if (i >= 2 * wp) return;
    const float* src = (i < wp) ? wk : wv;
    long j = (i < wp) ? i : i - wp;
    float2 v = ((const float2*)src)[j];
    split_pack(v.x, v.y, H[i], L[i]);
}

// merged prepack of wq and t2_w into separate buffers
__global__ void prepack_qt2_kernel(const float* __restrict__ wq,
                                   const float* __restrict__ t2w,
                                   unsigned* __restrict__ qH, unsigned* __restrict__ qL,
                                   unsigned* __restrict__ tH, unsigned* __restrict__ tL,
                                   long wp) {
    long i = (long)blockIdx.x * blockDim.x + threadIdx.x;
    if (i >= 2 * wp) return;
    if (i < wp) {
        float2 v = ((const float2*)wq)[i];
        split_pack(v.x, v.y, qH[i], qL[i]);
    } else {
        long j = i - wp;
        float2 v = ((const float2*)t2w)[j];
        split_pack(v.x, v.y, tH[j], tL[j]);
    }
}

// gather + positional embedding; emits packed hi/lo directly
__global__ void gather_pe_pack_kernel(const int* __restrict__ idx,
                                      const float* __restrict__ emb,
                                      unsigned* __restrict__ H,
                                      unsigned* __restrict__ L) {
    int i = blockIdx.x * blockDim.x + threadIdx.x;     // pair index
    if (i >= BB * SC * KP2) return;
    int pp  = i & (KP2 - 1);
    int row = i / KP2;
    int s   = row & (SC - 1);
    int g   = idx[row];
    int d0  = pp * 2;
    float freq = expf((float)d0 * -0.0179889460176f);  // -ln(10000)/512
    float ang  = (float)s * freq;
    float v0 = emb[(size_t)g * DM + d0]     + sinf(ang);
    float v1 = emb[(size_t)g * DM + d0 + 1] + cosf(ang);
    split_pack(v0, v1, H[i], L[i]);
}

__global__ void prepack_kernel(const float* __restrict__ in,
                               unsigned* __restrict__ H,
                               unsigned* __restrict__ L,
                               long npairs, int do_tanh) {
    long i = (long)blockIdx.x * blockDim.x + threadIdx.x;
    if (i >= npairs) return;
    float2 v = ((const float2*)in)[i];
    if (do_tanh) { v.x = tanhf(v.x); v.y = tanhf(v.y); }
    split_pack(v.x, v.y, H[i], L[i]);
}

// ---------------- mma / ldmatrix / cp.async helpers ----------------------------
__device__ __forceinline__ void mma_bf16(float* c, const unsigned* a, const unsigned* b) {
    asm("mma.sync.aligned.m16n8k16.row.col.f32.bf16.bf16.f32 "
        "{%0,%1,%2,%3}, {%4,%5,%6,%7}, {%8,%9}, {%0,%1,%2,%3};"
        : "+f"(c[0]), "+f"(c[1]), "+f"(c[2]), "+f"(c[3])
        : "r"(a[0]), "r"(a[1]), "r"(a[2]), "r"(a[3]), "r"(b[0]), "r"(b[1]));
}
__device__ __forceinline__ void cp16(void* dst, const void* src, bool ok) {
    unsigned d = (unsigned)__cvta_generic_to_shared(dst);
    int sz = ok ? 16 : 0;
    asm volatile("cp.async.cg.shared.global [%0], [%1], 16, %2;"
                 :: "r"(d), "l"(src), "r"(sz));
}
#define LDSM4(r, a)                                                          \
    asm volatile("ldmatrix.sync.aligned.m8n8.x4.shared.b16 {%0,%1,%2,%3}, [%4];" \
                 : "=r"((r)[0]), "=r"((r)[1]), "=r"((r)[2]), "=r"((r)[3])    \
                 : "r"(a))

#define PITCH 20
#define TSZ (128*PITCH)

// ======== fragment-load + mma block shared by all GEMM variants ==============
// Three product passes (hh, lh, hl): consecutive HMMAs hit independent acc
// tiles (16-deep ILP); per-tile accumulation order unchanged => bit-identical.
#define MMA_STEP(baseAH, baseAL, baseBH, baseBL)                                 \
    _Pragma("unroll")                                                            \
    for (int ks = 0; ks < 2; ++ks) {                                             \
        int kc = ks * 8;                                                         \
        unsigned ah[4][4], al[4][4];                                             \
        _Pragma("unroll")                                                        \
        for (int mt = 0; mt < 4; ++mt) {                                         \
            uint32_t off = (uint32_t)(((a_row + mt * 16) * PITCH + kc + a_col) * 4); \
            LDSM4(ah[mt], (baseAH) + off);                                       \
            LDSM4(al[mt], (baseAL) + off);                                       \
        }                                                                        \
        unsigned bh[4][2], bl[4][2];                                             \
        _Pragma("unroll")                                                        \
        for (int np = 0; np < 2; ++np) {                                         \
            uint32_t off = (uint32_t)(((b_row + np * 16) * PITCH + kc + b_col) * 4); \
            unsigned rh[4], rl[4];                                               \
            LDSM4(rh, (baseBH) + off);                                           \
            LDSM4(rl, (baseBL) + off);                                           \
            bh[np * 2][0]     = rh[0]; bh[np * 2][1]     = rh[1];                \
            bh[np * 2 + 1][0] = rh[2]; bh[np * 2 + 1][1] = rh[3];                \
            bl[np * 2][0]     = rl[0]; bl[np * 2][1]     = rl[1];                \
            bl[np * 2 + 1][0] = rl[2]; bl[np * 2 + 1][1] = rl[3];                \
        }                                                                        \
        _Pragma("unroll")                                                        \
        for (int mt = 0; mt < 4; ++mt)                                           \
            _Pragma("unroll")                                                    \
            for (int nt = 0; nt < 4; ++nt)                                       \
                mma_bf16(acc[mt][nt], ah[mt], bh[nt]);                           \
        _Pragma("unroll")                                                        \
        for (int mt = 0; mt < 4; ++mt)                                           \
            _Pragma("unroll")                                                    \
            for (int nt = 0; nt < 4; ++nt)                                       \
                mma_bf16(acc[mt][nt], al[mt], bh[nt]);                           \
        _Pragma("unroll")                                                        \
        for (int mt = 0; mt < 4; ++mt)                                           \
            _Pragma("unroll")                                                    \
            for (int nt = 0; nt < 4; ++nt)                                       \
                mma_bf16(acc[mt][nt], ah[mt], bl[nt]);                           \
    }

#define GEMM_PROLOG()                                                            \
    int bm = blockIdx.x * 128;                                                   \
    int bn = blockIdx.y * 128;                                                   \
    int tid = threadIdx.x;                                                       \
    int wid = tid >> 5;                                                          \
    int lane = tid & 31;                                                         \
    int warp_m = wid >> 2;                                                       \
    int warp_n = wid & 3;                                                        \
    int g  = lane >> 2;                                                          \
    int tg = lane & 3;                                                           \
    int m_base = warp_m * 64;                                                    \
    int n_base = warp_n * 32;                                                    \
    int a_row = m_base + (lane & 15);                                            \
    int a_col = (lane >> 4) * 4;                                                 \
    int b_row = n_base + ((lane >> 4) & 1) * 8 + (lane & 7);                     \
    int b_col = ((lane >> 3) & 1) * 4;                                           \
    float acc[4][4][4];                                                          \
    _Pragma("unroll")                                                            \
    for (int mt = 0; mt < 4; ++mt)                                               \
        _Pragma("unroll")                                                        \
        for (int nt = 0; nt < 4; ++nt)                                           \
            _Pragma("unroll")                                                    \
            for (int i = 0; i < 4; ++i) acc[mt][nt][i] = 0.f;                    \
    int srow0 = tid >> 2;                                                        \
    int sc4   = (tid & 3) * 4;                                                   \
    int srow1 = (tid + 256) >> 2;

#define STAGE_PK(buf, k0p)                                                       \
    {                                                                            \
        unsigned* bAH = sm + (buf) * 4 * TSZ;                                    \
        unsigned* bAL = bAH + TSZ;                                               \
        unsigned* bBH = bAH + 2 * TSZ;                                           \
        unsigned* bBL = bAH + 3 * TSZ;                                           \
        _Pragma("unroll")                                                        \
        for (int i = 0; i < 2; ++i) {                                            \
            int row = i ? srow1 : srow0;                                         \
            cp16(bAH + row * PITCH + sc4, AH + (size_t)(bm + row) * KP2 + (k0p) + sc4, true); \
            cp16(bAL + row * PITCH + sc4, AL + (size_t)(bm + row) * KP2 + (k0p) + sc4, true); \
            int nrow = bn + row;                                                 \
            bool ok = nrow < N;                                                  \
            size_t bro = (size_t)(ok ? nrow : 0) * KP2 + (k0p) + sc4;            \
            cp16(bBH + row * PITCH + sc4, BH + bro, ok);                         \
            cp16(bBL + row * PITCH + sc4, BL + bro, ok);                         \
        }                                                                        \
        asm volatile("cp.async.commit_group;");                                  \
    }

#define GEMM_MAINLOOP()                                                          \
    STAGE_PK(0, 0);                                                              \
    const int NSTEP = DM / 32;                                                   \
    for (int s = 0; s < NSTEP; ++s) {                                            \
        if (s + 1 < NSTEP) {                                                     \
            STAGE_PK((s + 1) & 1, (s + 1) * 16);                                 \
            asm volatile("cp.async.wait_group 1;");                              \
        } else {                                                                 \
            asm volatile("cp.async.wait_group 0;");                              \
        }                                                                        \
        __syncthreads();                                                         \
        uint32_t baseAH = smem_u32 + ((s & 1) * 4 * TSZ) * 4;                    \
        MMA_STEP(baseAH, baseAH + TSZ * 4, baseAH + 2 * TSZ * 4, baseAH + 3 * TSZ * 4); \
        __syncthreads();                                                         \
    }

// ---------------- GEMM variant 1: packed A/B, f32 C + bias --------------------
__global__ __launch_bounds__(256, 2)
void gemm_pk_kernel(const unsigned* __restrict__ AH, const unsigned* __restrict__ AL,
                    const unsigned* __restrict__ BH, const unsigned* __restrict__ BL,
                    const float* __restrict__ bias,
                    float* __restrict__ C,
                    int M, int N, int ldc) {
    extern __shared__ unsigned sm[];
    uint32_t smem_u32 = (uint32_t)__cvta_generic_to_shared(sm);
    GEMM_PROLOG();
    GEMM_MAINLOOP();

#pragma unroll
    for (int mt = 0; mt < 4; ++mt) {
        int row0 = bm + m_base + mt * 16 + g;
#pragma unroll
        for (int nt = 0; nt < 4; ++nt) {
            int col0 = bn + n_base + nt * 8 + 2 * tg;
            float b0 = bias ? bias[col0] : 0.f;
            float b1 = bias ? bias[col0 + 1] : 0.f;
            C[(size_t)row0 * ldc + col0]           = acc[mt][nt][0] + b0;
            C[(size_t)row0 * ldc + col0 + 1]       = acc[mt][nt][1] + b1;
            C[(size_t)(row0 + 8) * ldc + col0]     = acc[mt][nt][2] + b0;
            C[(size_t)(row0 + 8) * ldc + col0 + 1] = acc[mt][nt][3] + b1;
        }
    }
}

// ---------------- GEMM variant 1b: Q projection with fused mask gather --------
// A rows are indirected through mask_pos: global row r -> curr row (r/16)*SC + mask_pos[r].
// Identical values to gather-then-GEMM => bit-identical output.
__global__ __launch_bounds__(256, 2)
void gemm_pk_qproj_kernel(const int* __restrict__ mask_pos,
                          const unsigned* __restrict__ AH, const unsigned* __restrict__ AL,
                          const unsigned* __restrict__ BH, const unsigned* __restrict__ BL,
                          const float* __restrict__ bias,
                          float* __restrict__ C) {
    extern __shared__ unsigned sm[];
    uint32_t smem_u32 = (uint32_t)__cvta_generic_to_shared(sm);
    const int N = DM, ldc = DM;
    GEMM_PROLOG();

    // loop-invariant A row indirection (two staged rows per thread)
    int gr0 = bm + srow0;
    int gr1 = bm + srow1;
    size_t abase0 = (((size_t)(gr0 >> 4)) * SC + mask_pos[gr0]) * KP2 + sc4;
    size_t abase1 = (((size_t)(gr1 >> 4)) * SC + mask_pos[gr1]) * KP2 + sc4;

#define STAGE_QP(buf, k0p)                                                       \
    {                                                                            \
        unsigned* bAH = sm + (buf) * 4 * TSZ;                                    \
        unsigned* bAL = bAH + TSZ;                                               \
        unsigned* bBH = bAH + 2 * TSZ;                                           \
        unsigned* bBL = bAH + 3 * TSZ;                                           \
        cp16(bAH + srow0 * PITCH + sc4, AH + abase0 + (k0p), true);              \
        cp16(bAL + srow0 * PITCH + sc4, AL + abase0 + (k0p), true);              \
        cp16(bAH + srow1 * PITCH + sc4, AH + abase1 + (k0p), true);              \
        cp16(bAL + srow1 * PITCH + sc4, AL + abase1 + (k0p), true);              \
        cp16(bBH + srow0 * PITCH + sc4, BH + (size_t)(bn + srow0) * KP2 + (k0p) + sc4, true); \
        cp16(bBL + srow0 * PITCH + sc4, BL + (size_t)(bn + srow0) * KP2 + (k0p) + sc4, true); \
        cp16(bBH + srow1 * PITCH + sc4, BH + (size_t)(bn + srow1) * KP2 + (k0p) + sc4, true); \
        cp16(bBL + srow1 * PITCH + sc4, BL + (size_t)(bn + srow1) * KP2 + (k0p) + sc4, true); \
        asm volatile("cp.async.commit_group;");                                  \
    }

    STAGE_QP(0, 0);
    const int NSTEP = DM / 32;
    for (int s = 0; s < NSTEP; ++s) {
        if (s + 1 < NSTEP) {
            STAGE_QP((s + 1) & 1, (s + 1) * 16);
            asm volatile("cp.async.wait_group 1;");
        } else {
            asm volatile("cp.async.wait_group 0;");
        }
        __syncthreads();
        uint32_t baseAH = smem_u32 + ((s & 1) * 4 * TSZ) * 4;
        MMA_STEP(baseAH, baseAH + TSZ * 4, baseAH + 2 * TSZ * 4, baseAH + 3 * TSZ * 4);
        __syncthreads();
    }
#undef STAGE_QP

#pragma unroll
    for (int mt = 0; mt < 4; ++mt) {
        int row0 = bm + m_base + mt * 16 + g;
#pragma unroll
        for (int nt = 0; nt < 4; ++nt) {
            int col0 = bn + n_base + nt * 8 + 2 * tg;
            float b0 = bias[col0], b1 = bias[col0 + 1];
            C[(size_t)row0 * ldc + col0]           = acc[mt][nt][0] + b0;
            C[(size_t)row0 * ldc + col0 + 1]       = acc[mt][nt][1] + b1;
            C[(size_t)(row0 + 8) * ldc + col0]     = acc[mt][nt][2] + b0;
            C[(size_t)(row0 + 8) * ldc + col0 + 1] = acc[mt][nt][3] + b1;
        }
    }
}

// ---------------- GEMM variant 2: packed A/B, packed-out C (for t2) -----------
__global__ __launch_bounds__(256, 2)
void gemm_pk_packout_kernel(const unsigned* __restrict__ AH, const unsigned* __restrict__ AL,
                            const unsigned* __restrict__ BH, const unsigned* __restrict__ BL,
                            const float* __restrict__ bias,
                            unsigned* __restrict__ CH, unsigned* __restrict__ CL,
                            int M, int N) {
    extern __shared__ unsigned sm[];
    uint32_t smem_u32 = (uint32_t)__cvta_generic_to_shared(sm);
    GEMM_PROLOG();
    GEMM_MAINLOOP();

#pragma unroll
    for (int mt = 0; mt < 4; ++mt) {
        int row0 = bm + m_base + mt * 16 + g;
#pragma unroll
        for (int nt = 0; nt < 4; ++nt) {
            int col0 = bn + n_base + nt * 8 + 2 * tg;
            float b0 = bias[col0], b1 = bias[col0 + 1];
            float v0 = acc[mt][nt][0] + b0, v1 = acc[mt][nt][1] + b1;
            float v2 = acc[mt][nt][2] + b0, v3 = acc[mt][nt][3] + b1;
            size_t p0 = (size_t)row0 * KP2 + (col0 >> 1);
            size_t p1 = (size_t)(row0 + 8) * KP2 + (col0 >> 1);
            split_pack(v0, v1, CH[p0], CL[p0]);
            split_pack(v2, v3, CH[p1], CL[p1]);
        }
    }
}

// ---------------- GEMM variant 3: packed A/B, C + LSE partials (scores) --------
__global__ __launch_bounds__(256, 2)
void gemm_pk_score_kernel(const unsigned* __restrict__ AH, const unsigned* __restrict__ AL,
                          const unsigned* __restrict__ BH, const unsigned* __restrict__ BL,
                          float* __restrict__ C,
                          float2* __restrict__ part,
                          int N) {
    extern __shared__ unsigned sm[];
    uint32_t smem_u32 = (uint32_t)__cvta_generic_to_shared(sm);
    GEMM_PROLOG();
    GEMM_MAINLOOP();

    // epilogue: store C + per-row (max, sumexp) partials, reduced in smem
    float2* red = (float2*)sm;     // [128][16] = 16 KB, staging buffer reuse
#pragma unroll
    for (int mt = 0; mt < 4; ++mt) {
        int rl0 = m_base + mt * 16 + g;
        int row0 = bm + rl0;
        float m0 = -INFINITY, s0 = 0.f, m1 = -INFINITY, s1 = 0.f;
#pragma unroll
        for (int nt = 0; nt < 4; ++nt) {
            int col0 = bn + n_base + nt * 8 + 2 * tg;
            float v00 = acc[mt][nt][0], v01 = acc[mt][nt][1];
            float v10 = acc[mt][nt][2], v11 = acc[mt][nt][3];
            if (col0 < N) {
                C[(size_t)row0 * N + col0]       = v00;
                C[(size_t)(row0 + 8) * N + col0] = v10;
                float nm0 = fmaxf(m0, v00); s0 = s0 * __expf(m0 - nm0) + __expf(v00 - nm0); m0 = nm0;
                float nm1 = fmaxf(m1, v10); s1 = s1 * __expf(m1 - nm1) + __expf(v10 - nm1); m1 = nm1;
            }
            if (col0 + 1 < N) {
                C[(size_t)row0 * N + col0 + 1]       = v01;
                C[(size_t)(row0 + 8) * N + col0 + 1] = v11;
                float nm0 = fmaxf(m0, v01); s0 = s0 * __expf(m0 - nm0) + __expf(v01 - nm0); m0 = nm0;
                float nm1 = fmaxf(m1, v11); s1 = s1 * __expf(m1 - nm1) + __expf(v11 - nm1); m1 = nm1;
            }
        }
        int slot = warp_n * 4 + tg;
        red[rl0 * 16 + slot]       = make_float2(m0, s0);
        red[(rl0 + 8) * 16 + slot] = make_float2(m1, s1);
    }
    __syncthreads();
    if (tid < 128) {
        float m = -INFINITY, s = 0.f;
#pragma unroll
        for (int k = 0; k < 16; ++k) {
            float2 v = red[tid * 16 + k];
            float nm = fmaxf(m, v.x);
            s = s * __expf(m - nm) + v.y * __expf(v.x - nm);
            m = nm;
        }
        part[(size_t)blockIdx.y * MQ + bm + tid] = make_float2(m, s);
    }
}

// ---------------- attention (reads merged KV, ld=1024) ------------------------
__global__ __launch_bounds__(256)
void attn_kernel(const float* __restrict__ Q,
                 const float* __restrict__ KV,
                 float* __restrict__ out) {
    int blk = blockIdx.x;
    int b = blk / HH, h = blk % HH;

    __shared__ float sQ[NM][DH];
    __shared__ float sS[NM][SC];
    __shared__ float sKV[SC][DH + 1];

    int tid = threadIdx.x;

    for (int e = tid; e < NM * DH; e += 256) {
        int m = e / DH, d0 = e % DH;
        sQ[m][d0] = Q[((size_t)b * NM + m) * DM + h * DH + d0];
    }
    for (int e = tid; e < SC * DH; e += 256) {
        int k = e / DH, d0 = e % DH;
        sKV[k][d0] = KV[((size_t)b * SC + k) * 1024 + h * DH + d0];
    }
    __syncthreads();

    for (int e = tid; e < NM * SC; e += 256) {
        int m = e / SC, k = e % SC;
        float acc = 0.f;
#pragma unroll
        for (int d0 = 0; d0 < DH; ++d0) acc += sQ[m][d0] * sKV[k][d0];
        sS[m][k] = acc;
    }
    __syncthreads();

    int w = tid >> 5, lane = tid & 31;
    for (int m = 2 * w; m < 2 * w + 2; ++m) {
        float vals[4];
        float mx = -INFINITY;
#pragma unroll
        for (int j = 0; j < 4; ++j) {
            vals[j] = sS[m][lane * 4 + j];
            mx = fmaxf(mx, vals[j]);
        }
#pragma unroll
        for (int off = 16; off; off >>= 1)
            mx = fmaxf(mx, __shfl_xor_sync(0xffffffffu, mx, off));
        float sum = 0.f;
#pragma unroll
        for (int j = 0; j < 4; ++j) {
            vals[j] = expf(vals[j] - mx);
            sum += vals[j];
        }
#pragma unroll
        for (int off = 16; off; off >>= 1)
            sum += __shfl_xor_sync(0xffffffffu, sum, off);
        float inv = 1.f / sum;
#pragma unroll
        for (int j = 0; j < 4; ++j) sS[m][lane * 4 + j] = vals[j] * inv;
    }
    __syncthreads();

    for (int e = tid; e < SC * DH; e += 256) {
        int k = e / DH, d0 = e % DH;
        sKV[k][d0] = KV[((size_t)b * SC + k) * 1024 + 512 + h * DH + d0];
    }
    __syncthreads();

    for (int e = tid; e < NM * DH; e += 256) {
        int m = e / DH, d0 = e % DH;
        float acc = 0.f;
#pragma unroll
        for (int k = 0; k < SC; ++k) acc += sS[m][k] * sKV[k][d0];
        out[((size_t)b * NM + m) * DM + h * DH + d0] = acc;
    }
}

// ---------------- LSE reduce + subtract ---------------------------------------
__global__ void lse_reduce_kernel(const float2* __restrict__ part,
                                  float* __restrict__ lse) {
    int row = blockIdx.x;
    int lane = threadIdx.x;
    float m = -INFINITY, s = 0.f;
    for (int c = lane; c < NCHUNK; c += 32) {
        float2 v = part[(size_t)c * MQ + row];
        float nm = fmaxf(m, v.x);
        s = s * __expf(m - nm) + v.y * __expf(v.x - nm);
        m = nm;
    }
#pragma unroll
    for (int off = 16; off; off >>= 1) {
        float m2 = __shfl_xor_sync(0xffffffffu, m, off);
        float s2 = __shfl_xor_sync(0xffffffffu, s, off);
        float nm = fmaxf(m, m2);
        s = s * __expf(m - nm) + s2 * __expf(m2 - nm);
        m = nm;
    }
    if (lane == 0) lse[row] = m + logf(s);
}

__global__ __launch_bounds__(256)
void subtract_kernel(float* __restrict__ out, const float* __restrict__ lse) {
    int row = blockIdx.x;
    float l = lse[row];
    float* p = out + (size_t)row * NC;
    for (int i = threadIdx.x; i < NC; i += 256) p[i] -= l;
}

// ---------------- launch -----------------------------------------------------
extern "C" void kernel_launch(void* const* d_in, const int* in_sizes, int n_in,
                              void* d_out, int out_size) {
    const int*   mask_pos  = (const int*)d_in[2];
    const int*   mask_curr = (const int*)d_in[3];
    const float* emb       = (const float*)d_in[5];
    const float* c_wq = (const float*)d_in[12];
    const float* c_bq = (const float*)d_in[13];
    const float* c_wk = (const float*)d_in[14];
    const float* c_bk = (const float*)d_in[15];
    const float* c_wv = (const float*)d_in[16];
    const float* c_bv = (const float*)d_in[17];
    const float* t2_w = (const float*)d_in[24];
    const float* t2_b = (const float*)d_in[25];
    float* out = (float*)d_out;

    float *KV, *Qb, *attn, *bKV, *lse;
    float2* part;
    cudaGetSymbolAddress((void**)&KV,   g_KV);
    cudaGetSymbolAddress((void**)&Qb,   g_Q);
    cudaGetSymbolAddress((void**)&attn, g_attn);
    cudaGetSymbolAddress((void**)&bKV,  g_bKV);
    cudaGetSymbolAddress((void**)&part, g_part);
    cudaGetSymbolAddress((void**)&lse,  g_lse);

    unsigned *embH, *embL, *currH, *currL, *wkvH, *wkvL, *wqH, *wqL, *t2H, *t2L;
    unsigned *tanhH, *tanhL, *hybH, *hybL;
    cudaGetSymbolAddress((void**)&embH,  g_pk_embH);
    cudaGetSymbolAddress((void**)&embL,  g_pk_embL);
    cudaGetSymbolAddress((void**)&currH, g_pk_currH);
    cudaGetSymbolAddress((void**)&currL, g_pk_currL);
    cudaGetSymbolAddress((void**)&wkvH,  g_pk_wkvH);
    cudaGetSymbolAddress((void**)&wkvL,  g_pk_wkvL);
    cudaGetSymbolAddress((void**)&wqH,   g_pk_wqH);
    cudaGetSymbolAddress((void**)&wqL,   g_pk_wqL);
    cudaGetSymbolAddress((void**)&t2H,   g_pk_t2H);
    cudaGetSymbolAddress((void**)&t2L,   g_pk_t2L);
    cudaGetSymbolAddress((void**)&tanhH, g_pk_tanhH);
    cudaGetSymbolAddress((void**)&tanhL, g_pk_tanhL);
    cudaGetSymbolAddress((void**)&hybH,  g_pk_hybH);
    cudaGetSymbolAddress((void**)&hybL,  g_pk_hybL);

    const int SMEMB = 2 * 4 * TSZ * 4;    // 81920 B
    cudaFuncSetAttribute(gemm_pk_kernel,
                         cudaFuncAttributeMaxDynamicSharedMemorySize, SMEMB);
    cudaFuncSetAttribute(gemm_pk_qproj_kernel,
                         cudaFuncAttributeMaxDynamicSharedMemorySize, SMEMB);
    cudaFuncSetAttribute(gemm_pk_packout_kernel,
                         cudaFuncAttributeMaxDynamicSharedMemorySize, SMEMB);
    cudaFuncSetAttribute(gemm_pk_score_kernel,
                         cudaFuncAttributeMaxDynamicSharedMemorySize, SMEMB);

    const long WP = (long)DM * KP2;        // pairs per 512x512 matrix

    // launch 0: merged wk|wv prepack
    prepack_kv_kernel<<<(int)((2 * WP + 255) / 256), 256>>>(c_wk, c_wv, wkvH, wkvL, WP);
    // launch 1: merged wq + t2 prepack
    prepack_qt2_kernel<<<(int)((2 * WP + 255) / 256), 256>>>(c_wq, t2_w, wqH, wqL, t2H, t2L, WP);
    // launch 2: bias concat
    concat_bias_kernel<<<4, 256>>>(c_bk, c_bv, bKV);
    // launch 3: curr = emb[mask_curr] + PE, packed directly
    gather_pe_pack_kernel<<<(BB * SC * KP2 + 255) / 256, 256>>>(mask_curr, emb,
                                                                currH, currL);
    // launch 4: emb prepack (candidate rows)
    {
        long np = (long)NC * KP2;
        prepack_kernel<<<(int)((np + 255) / 256), 256>>>(emb + 2 * DM, embH, embL, np, 0);
    }
    // launch 5: merged K|V projection [4096, 1024]  (ncu -s 5 captures THIS)
    {
        dim3 g((BB * SC) / 128, 1024 / 128);
        gemm_pk_kernel<<<g, 256, SMEMB>>>(currH, currL, wkvH, wkvL, bKV, KV,
                                          BB * SC, 1024, 1024);
    }

    // Q projection with fused mask gather
    {
        dim3 g(MQ / 128, DM / 128);
        gemm_pk_qproj_kernel<<<g, 256, SMEMB>>>(mask_pos, currH, currL, wqH, wqL, c_bq, Qb);
    }

    // attention
    attn_kernel<<<BB * HH, 256>>>(Qb, KV, attn);

    // hyb = tanh(attn) @ t2_w^T + t2_b, emitted directly as packed hi/lo
    prepack_kernel<<<(MQ * KP2 + 255) / 256, 256>>>(attn, tanhH, tanhL, MQ * KP2, 1);
    {
        dim3 g(MQ / 128, DM / 128);
        gemm_pk_packout_kernel<<<g, 256, SMEMB>>>(tanhH, tanhL, t2H, t2L, t2_b,
                                                  hybH, hybL, MQ, DM);
    }

    // scores = hyb @ emb[2:]^T with fused LSE partials
    {
        dim3 g(MQ / 128, NCHUNK);
        gemm_pk_score_kernel<<<g, 256, SMEMB>>>(hybH, hybL, embH, embL, out, part, NC);
    }

    // lse reduce + subtract
    lse_reduce_kernel<<<MQ, 32>>>(part, lse);
    subtract_kernel<<<MQ, 256>>>(out, lse);
}

// round 12
// speedup vs baseline: 1.2655x; 1.0693x over previous
#include <cuda_runtime.h>
#include <cuda_bf16.h>
#include <math.h>
#include <stdint.h>

#define BB 32
#define SC 128
#define NM 16
#define DM 512
#define HH 8
#define DH 64
#define NC 39998
#define MQ (BB*NM)    /* 512 gathered query rows */
#define KP2 256       /* packed pairs per row (DM/2) */
#define NCHUNK 313    /* ceil(NC/128) */

// ---------------- scratch (device globals; no allocation allowed) -------------
__device__ float g_KV[BB*SC*1024];     // K cols 0..511, V cols 512..1023
__device__ float g_Q[MQ*DM];
__device__ float g_attn[MQ*DM];
__device__ float g_bKV[1024];
__device__ float2 g_part[NCHUNK*MQ];   // per (chunk,row) partial (max, sumexp)

// packed bf16 hi/lo operands
__device__ unsigned g_pk_currH[BB*SC*KP2];
__device__ unsigned g_pk_currL[BB*SC*KP2];
__device__ unsigned g_pk_wkvH[1024*KP2];
__device__ unsigned g_pk_wkvL[1024*KP2];
__device__ unsigned g_pk_wqH[DM*KP2];
__device__ unsigned g_pk_wqL[DM*KP2];
__device__ unsigned g_pk_t2H[DM*KP2];
__device__ unsigned g_pk_t2L[DM*KP2];
__device__ unsigned g_pk_tanhH[MQ*KP2];
__device__ unsigned g_pk_tanhL[MQ*KP2];
__device__ unsigned g_pk_hybH[MQ*KP2];
__device__ unsigned g_pk_hybL[MQ*KP2];

// ---------------- bf16 split helper ------------------------------------------
__device__ __forceinline__ void split_pack(float x, float y,
                                           unsigned& hi, unsigned& lo) {
    __nv_bfloat16 hx = __float2bfloat16_rn(x);
    __nv_bfloat16 hy = __float2bfloat16_rn(y);
    float rx = x - __bfloat162float(hx);
    float ry = y - __bfloat162float(hy);
    __nv_bfloat16 lx = __float2bfloat16_rn(rx);
    __nv_bfloat16 ly = __float2bfloat16_rn(ry);
    hi = ((unsigned)__bfloat16_as_ushort(hy) << 16) | __bfloat16_as_ushort(hx);
    lo = ((unsigned)__bfloat16_as_ushort(ly) << 16) | __bfloat16_as_ushort(lx);
}

// ---------------- small elementwise kernels -----------------------------------
__global__ void concat_bias_kernel(const float* __restrict__ bk,
                                   const float* __restrict__ bv,
                                   float* __restrict__ out) {
    int t = blockIdx.x * blockDim.x + threadIdx.x;
    if (t < 512) out[t] = bk[t];
    else if (t < 1024) out[t] = bv[t - 512];
}

__global__ void prepack_kv_kernel(const float* __restrict__ wk,
                                  const float* __restrict__ wv,
                                  unsigned* __restrict__ H,
                                  unsigned* __restrict__ L,
                                  long wp) {
    long i = (long)blockIdx.x * blockDim.x + threadIdx.x;
    if (i >= 2 * wp) return;
    const float* src = (i < wp) ? wk : wv;
    long j = (i < wp) ? i : i - wp;
    float2 v = ((const float2*)src)[j];
    split_pack(v.x, v.y, H[i], L[i]);
}

__global__ void prepack_qt2_kernel(const float* __restrict__ wq,
                                   const float* __restrict__ t2w,
                                   unsigned* __restrict__ qH, unsigned* __restrict__ qL,
                                   unsigned* __restrict__ tH, unsigned* __restrict__ tL,
                                   long wp) {
    long i = (long)blockIdx.x * blockDim.x + threadIdx.x;
    if (i >= 2 * wp) return;
    if (i < wp) {
        float2 v = ((const float2*)wq)[i];
        split_pack(v.x, v.y, qH[i], qL[i]);
    } else {
        long j = i - wp;
        float2 v = ((const float2*)t2w)[j];
        split_pack(v.x, v.y, tH[j], tL[j]);
    }
}

// gather + positional embedding; emits packed hi/lo directly
__global__ void gather_pe_pack_kernel(const int* __restrict__ idx,
                                      const float* __restrict__ emb,
                                      unsigned* __restrict__ H,
                                      unsigned* __restrict__ L) {
    int i = blockIdx.x * blockDim.x + threadIdx.x;     // pair index
    if (i >= BB * SC * KP2) return;
    int pp  = i & (KP2 - 1);
    int row = i / KP2;
    int s   = row & (SC - 1);
    int g   = idx[row];
    int d0  = pp * 2;
    float freq = expf((float)d0 * -0.0179889460176f);  // -ln(10000)/512
    float ang  = (float)s * freq;
    float v0 = emb[(size_t)g * DM + d0]     + sinf(ang);
    float v1 = emb[(size_t)g * DM + d0 + 1] + cosf(ang);
    split_pack(v0, v1, H[i], L[i]);
}

__global__ void prepack_kernel(const float* __restrict__ in,
                               unsigned* __restrict__ H,
                               unsigned* __restrict__ L,
                               long npairs, int do_tanh) {
    long i = (long)blockIdx.x * blockDim.x + threadIdx.x;
    if (i >= npairs) return;
    float2 v = ((const float2*)in)[i];
    if (do_tanh) { v.x = tanhf(v.x); v.y = tanhf(v.y); }
    split_pack(v.x, v.y, H[i], L[i]);
}

// ---------------- mma / ldmatrix / cp.async helpers ----------------------------
__device__ __forceinline__ void mma_bf16(float* c, const unsigned* a, const unsigned* b) {
    asm("mma.sync.aligned.m16n8k16.row.col.f32.bf16.bf16.f32 "
        "{%0,%1,%2,%3}, {%4,%5,%6,%7}, {%8,%9}, {%0,%1,%2,%3};"
        : "+f"(c[0]), "+f"(c[1]), "+f"(c[2]), "+f"(c[3])
        : "r"(a[0]), "r"(a[1]), "r"(a[2]), "r"(a[3]), "r"(b[0]), "r"(b[1]));
}
__device__ __forceinline__ void cp16(void* dst, const void* src, bool ok) {
    unsigned d = (unsigned)__cvta_generic_to_shared(dst);
    int sz = ok ? 16 : 0;
    asm volatile("cp.async.cg.shared.global [%0], [%1], 16, %2;"
                 :: "r"(d), "l"(src), "r"(sz));
}
#define LDSM4(r, a)                                                          \
    asm volatile("ldmatrix.sync.aligned.m8n8.x4.shared.b16 {%0,%1,%2,%3}, [%4];" \
                 : "=r"((r)[0]), "=r"((r)[1]), "=r"((r)[2]), "=r"((r)[3])    \
                 : "r"(a))

#define PITCH 20
#define TSZ (128*PITCH)
#define F32SZ (128*32)   /* f32 B staging tile, uint32 units (16 KB) */

// ======== fragment-load + mma block shared by all GEMM variants ==============
#define MMA_STEP(baseAH, baseAL, baseBH, baseBL)                                 \
    _Pragma("unroll")                                                            \
    for (int ks = 0; ks < 2; ++ks) {                                             \
        int kc = ks * 8;                                                         \
        unsigned ah[4][4], al[4][4];                                             \
        _Pragma("unroll")                                                        \
        for (int mt = 0; mt < 4; ++mt) {                                         \
            uint32_t off = (uint32_t)(((a_row + mt * 16) * PITCH + kc + a_col) * 4); \
            LDSM4(ah[mt], (baseAH) + off);                                       \
            LDSM4(al[mt], (baseAL) + off);                                       \
        }                                                                        \
        unsigned bh[4][2], bl[4][2];                                             \
        _Pragma("unroll")                                                        \
        for (int np = 0; np < 2; ++np) {                                         \
            uint32_t off = (uint32_t)(((b_row + np * 16) * PITCH + kc + b_col) * 4); \
            unsigned rh[4], rl[4];                                               \
            LDSM4(rh, (baseBH) + off);                                           \
            LDSM4(rl, (baseBL) + off);                                           \
            bh[np * 2][0]     = rh[0]; bh[np * 2][1]     = rh[1];                \
            bh[np * 2 + 1][0] = rh[2]; bh[np * 2 + 1][1] = rh[3];                \
            bl[np * 2][0]     = rl[0]; bl[np * 2][1]     = rl[1];                \
            bl[np * 2 + 1][0] = rl[2]; bl[np * 2 + 1][1] = rl[3];                \
        }                                                                        \
        _Pragma("unroll")                                                        \
        for (int mt = 0; mt < 4; ++mt)                                           \
            _Pragma("unroll")                                                    \
            for (int nt = 0; nt < 4; ++nt)                                       \
                mma_bf16(acc[mt][nt], ah[mt], bh[nt]);                           \
        _Pragma("unroll")                                                        \
        for (int mt = 0; mt < 4; ++mt)                                           \
            _Pragma("unroll")                                                    \
            for (int nt = 0; nt < 4; ++nt)                                       \
                mma_bf16(acc[mt][nt], al[mt], bh[nt]);                           \
        _Pragma("unroll")                                                        \
        for (int mt = 0; mt < 4; ++mt)                                           \
            _Pragma("unroll")                                                    \
            for (int nt = 0; nt < 4; ++nt)                                       \
                mma_bf16(acc[mt][nt], ah[mt], bl[nt]);                           \
    }

#define GEMM_PROLOG()                                                            \
    int bm = blockIdx.x * 128;                                                   \
    int bn = blockIdx.y * 128;                                                   \
    int tid = threadIdx.x;                                                       \
    int wid = tid >> 5;                                                          \
    int lane = tid & 31;                                                         \
    int warp_m = wid >> 2;                                                       \
    int warp_n = wid & 3;                                                        \
    int g  = lane >> 2;                                                          \
    int tg = lane & 3;                                                           \
    int m_base = warp_m * 64;                                                    \
    int n_base = warp_n * 32;                                                    \
    int a_row = m_base + (lane & 15);                                            \
    int a_col = (lane >> 4) * 4;                                                 \
    int b_row = n_base + ((lane >> 4) & 1) * 8 + (lane & 7);                     \
    int b_col = ((lane >> 3) & 1) * 4;                                           \
    float acc[4][4][4];                                                          \
    _Pragma("unroll")                                                            \
    for (int mt = 0; mt < 4; ++mt)                                               \
        _Pragma("unroll")                                                        \
        for (int nt = 0; nt < 4; ++nt)                                           \
            _Pragma("unroll")                                                    \
            for (int i = 0; i < 4; ++i) acc[mt][nt][i] = 0.f;                    \
    int srow0 = tid >> 2;                                                        \
    int sc4   = (tid & 3) * 4;                                                   \
    int srow1 = (tid + 256) >> 2;

#define STAGE_PK(buf, k0p)                                                       \
    {                                                                            \
        unsigned* bAH = sm + (buf) * 4 * TSZ;                                    \
        unsigned* bAL = bAH + TSZ;                                               \
        unsigned* bBH = bAH + 2 * TSZ;                                           \
        unsigned* bBL = bAH + 3 * TSZ;                                           \
        _Pragma("unroll")                                                        \
        for (int i = 0; i < 2; ++i) {                                            \
            int row = i ? srow1 : srow0;                                         \
            cp16(bAH + row * PITCH + sc4, AH + (size_t)(bm + row) * KP2 + (k0p) + sc4, true); \
            cp16(bAL + row * PITCH + sc4, AL + (size_t)(bm + row) * KP2 + (k0p) + sc4, true); \
            int nrow = bn + row;                                                 \
            bool ok = nrow < N;                                                  \
            size_t bro = (size_t)(ok ? nrow : 0) * KP2 + (k0p) + sc4;            \
            cp16(bBH + row * PITCH + sc4, BH + bro, ok);                         \
            cp16(bBL + row * PITCH + sc4, BL + bro, ok);                         \
        }                                                                        \
        asm volatile("cp.async.commit_group;");                                  \
    }

#define GEMM_MAINLOOP()                                                          \
    STAGE_PK(0, 0);                                                              \
    const int NSTEP = DM / 32;                                                   \
    for (int s = 0; s < NSTEP; ++s) {                                            \
        if (s + 1 < NSTEP) {                                                     \
            STAGE_PK((s + 1) & 1, (s + 1) * 16);                                 \
            asm volatile("cp.async.wait_group 1;");                              \
        } else {                                                                 \
            asm volatile("cp.async.wait_group 0;");                              \
        }                                                                        \
        __syncthreads();                                                         \
        uint32_t baseAH = smem_u32 + ((s & 1) * 4 * TSZ) * 4;                    \
        MMA_STEP(baseAH, baseAH + TSZ * 4, baseAH + 2 * TSZ * 4, baseAH + 3 * TSZ * 4); \
        __syncthreads();                                                         \
    }

// ---------------- GEMM variant 1: packed A/B, f32 C + bias --------------------
__global__ __launch_bounds__(256, 2)
void gemm_pk_kernel(const unsigned* __restrict__ AH, const unsigned* __restrict__ AL,
                    const unsigned* __restrict__ BH, const unsigned* __restrict__ BL,
                    const float* __restrict__ bias,
                    float* __restrict__ C,
                    int M, int N, int ldc) {
    extern __shared__ unsigned sm[];
    uint32_t smem_u32 = (uint32_t)__cvta_generic_to_shared(sm);
    GEMM_PROLOG();
    GEMM_MAINLOOP();

#pragma unroll
    for (int mt = 0; mt < 4; ++mt) {
        int row0 = bm + m_base + mt * 16 + g;
#pragma unroll
        for (int nt = 0; nt < 4; ++nt) {
            int col0 = bn + n_base + nt * 8 + 2 * tg;
            float b0 = bias ? bias[col0] : 0.f;
            float b1 = bias ? bias[col0 + 1] : 0.f;
            C[(size_t)row0 * ldc + col0]           = acc[mt][nt][0] + b0;
            C[(size_t)row0 * ldc + col0 + 1]       = acc[mt][nt][1] + b1;
            C[(size_t)(row0 + 8) * ldc + col0]     = acc[mt][nt][2] + b0;
            C[(size_t)(row0 + 8) * ldc + col0 + 1] = acc[mt][nt][3] + b1;
        }
    }
}

// ---------------- GEMM variant 1b: Q projection with fused mask gather --------
__global__ __launch_bounds__(256, 2)
void gemm_pk_qproj_kernel(const int* __restrict__ mask_pos,
                          const unsigned* __restrict__ AH, const unsigned* __restrict__ AL,
                          const unsigned* __restrict__ BH, const unsigned* __restrict__ BL,
                          const float* __restrict__ bias,
                          float* __restrict__ C) {
    extern __shared__ unsigned sm[];
    uint32_t smem_u32 = (uint32_t)__cvta_generic_to_shared(sm);
    const int N = DM, ldc = DM;
    GEMM_PROLOG();

    int gr0 = bm + srow0;
    int gr1 = bm + srow1;
    size_t abase0 = (((size_t)(gr0 >> 4)) * SC + mask_pos[gr0]) * KP2 + sc4;
    size_t abase1 = (((size_t)(gr1 >> 4)) * SC + mask_pos[gr1]) * KP2 + sc4;

#define STAGE_QP(buf, k0p)                                                       \
    {                                                                            \
        unsigned* bAH = sm + (buf) * 4 * TSZ;                                    \
        unsigned* bAL = bAH + TSZ;                                               \
        unsigned* bBH = bAH + 2 * TSZ;                                           \
        unsigned* bBL = bAH + 3 * TSZ;                                           \
        cp16(bAH + srow0 * PITCH + sc4, AH + abase0 + (k0p), true);              \
        cp16(bAL + srow0 * PITCH + sc4, AL + abase0 + (k0p), true);              \
        cp16(bAH + srow1 * PITCH + sc4, AH + abase1 + (k0p), true);              \
        cp16(bAL + srow1 * PITCH + sc4, AL + abase1 + (k0p), true);              \
        cp16(bBH + srow0 * PITCH + sc4, BH + (size_t)(bn + srow0) * KP2 + (k0p) + sc4, true); \
        cp16(bBL + srow0 * PITCH + sc4, BL + (size_t)(bn + srow0) * KP2 + (k0p) + sc4, true); \
        cp16(bBH + srow1 * PITCH + sc4, BH + (size_t)(bn + srow1) * KP2 + (k0p) + sc4, true); \
        cp16(bBL + srow1 * PITCH + sc4, BL + (size_t)(bn + srow1) * KP2 + (k0p) + sc4, true); \
        asm volatile("cp.async.commit_group;");                                  \
    }

    STAGE_QP(0, 0);
    const int NSTEP = DM / 32;
    for (int s = 0; s < NSTEP; ++s) {
        if (s + 1 < NSTEP) {
            STAGE_QP((s + 1) & 1, (s + 1) * 16);
            asm volatile("cp.async.wait_group 1;");
        } else {
            asm volatile("cp.async.wait_group 0;");
        }
        __syncthreads();
        uint32_t baseAH = smem_u32 + ((s & 1) * 4 * TSZ) * 4;
        MMA_STEP(baseAH, baseAH + TSZ * 4, baseAH + 2 * TSZ * 4, baseAH + 3 * TSZ * 4);
        __syncthreads();
    }
#undef STAGE_QP

#pragma unroll
    for (int mt = 0; mt < 4; ++mt) {
        int row0 = bm + m_base + mt * 16 + g;
#pragma unroll
        for (int nt = 0; nt < 4; ++nt) {
            int col0 = bn + n_base + nt * 8 + 2 * tg;
            float b0 = bias[col0], b1 = bias[col0 + 1];
            C[(size_t)row0 * ldc + col0]           = acc[mt][nt][0] + b0;
            C[(size_t)row0 * ldc + col0 + 1]       = acc[mt][nt][1] + b1;
            C[(size_t)(row0 + 8) * ldc + col0]     = acc[mt][nt][2] + b0;
            C[(size_t)(row0 + 8) * ldc + col0 + 1] = acc[mt][nt][3] + b1;
        }
    }
}

// ---------------- GEMM variant 2: packed A/B, packed-out C (for t2) -----------
__global__ __launch_bounds__(256, 2)
void gemm_pk_packout_kernel(const unsigned* __restrict__ AH, const unsigned* __restrict__ AL,
                            const unsigned* __restrict__ BH, const unsigned* __restrict__ BL,
                            const float* __restrict__ bias,
                            unsigned* __restrict__ CH, unsigned* __restrict__ CL,
                            int M, int N) {
    extern __shared__ unsigned sm[];
    uint32_t smem_u32 = (uint32_t)__cvta_generic_to_shared(sm);
    GEMM_PROLOG();
    GEMM_MAINLOOP();

#pragma unroll
    for (int mt = 0; mt < 4; ++mt) {
        int row0 = bm + m_base + mt * 16 + g;
#pragma unroll
        for (int nt = 0; nt < 4; ++nt) {
            int col0 = bn + n_base + nt * 8 + 2 * tg;
            float b0 = bias[col0], b1 = bias[col0 + 1];
            float v0 = acc[mt][nt][0] + b0, v1 = acc[mt][nt][1] + b1;
            float v2 = acc[mt][nt][2] + b0, v3 = acc[mt][nt][3] + b1;
            size_t p0 = (size_t)row0 * KP2 + (col0 >> 1);
            size_t p1 = (size_t)(row0 + 8) * KP2 + (col0 >> 1);
            split_pack(v0, v1, CH[p0], CL[p0]);
            split_pack(v2, v3, CH[p1], CL[p1]);
        }
    }
}

// ---------------- GEMM variant 3: scores, f32 B (emb) converted in-kernel ------
// smem: 2 packed buffers (80 KB) + 2 f32 B staging tiles (32 KB) = 112 KB.
// Conversion bits identical to split_pack => bit-identical GEMM vs prepacked B.
__global__ __launch_bounds__(256, 2)
void gemm_score_kernel(const unsigned* __restrict__ AH, const unsigned* __restrict__ AL,
                       const float* __restrict__ Bf,   // emb + 2*DM, rows of 512 f32
                       float* __restrict__ C,
                       float2* __restrict__ part,
                       int N) {
    extern __shared__ unsigned sm[];
    uint32_t smem_u32 = (uint32_t)__cvta_generic_to_shared(sm);
    GEMM_PROLOG();
    (void)b_row; (void)b_col;   // still used by MMA_STEP
    int brow = tid >> 3;        // 0..31, B f32 staging row group
    int bq   = (tid & 7) * 4;   // float col within 32

#define STAGE_SC(buf, s)                                                         \
    {                                                                            \
        unsigned* bAH = sm + (buf) * 4 * TSZ;                                    \
        unsigned* bAL = bAH + TSZ;                                               \
        float* bF = (float*)(sm + 8 * TSZ + (buf) * F32SZ);                      \
        int k0p = (s) * 16;                                                      \
        cp16(bAH + srow0 * PITCH + sc4, AH + (size_t)(bm + srow0) * KP2 + k0p + sc4, true); \
        cp16(bAL + srow0 * PITCH + sc4, AL + (size_t)(bm + srow0) * KP2 + k0p + sc4, true); \
        cp16(bAH + srow1 * PITCH + sc4, AH + (size_t)(bm + srow1) * KP2 + k0p + sc4, true); \
        cp16(bAL + srow1 * PITCH + sc4, AL + (size_t)(bm + srow1) * KP2 + k0p + sc4, true); \
        _Pragma("unroll")                                                        \
        for (int j = 0; j < 4; ++j) {                                            \
            int row = brow + j * 32;                                             \
            int nrow = bn + row;                                                 \
            bool ok = nrow < N;                                                  \
            cp16(bF + row * 32 + bq,                                             \
                 Bf + (size_t)(ok ? nrow : 0) * DM + (s) * 32 + bq, ok);         \
        }                                                                        \
        asm volatile("cp.async.commit_group;");                                  \
    }

    STAGE_SC(0, 0);
    const int NSTEP = DM / 32;
    for (int s = 0; s < NSTEP; ++s) {
        if (s + 1 < NSTEP) {
            STAGE_SC((s + 1) & 1, s + 1);
            asm volatile("cp.async.wait_group 1;");
        } else {
            asm volatile("cp.async.wait_group 0;");
        }
        __syncthreads();

        // convert f32 B -> packed hi/lo (bit-identical to split_pack)
        {
            unsigned* bAH0 = sm + (s & 1) * 4 * TSZ;
            unsigned* bBH = bAH0 + 2 * TSZ;
            unsigned* bBL = bAH0 + 3 * TSZ;
            const float* bF = (const float*)(sm + 8 * TSZ + (s & 1) * F32SZ);
#pragma unroll
            for (int j = 0; j < 8; ++j) {
                int idx = tid + j * 256;
                int row = idx >> 4;
                int p   = idx & 15;
                float x = bF[row * 32 + 2 * p];
                float y = bF[row * 32 + 2 * p + 1];
                unsigned hi;
                asm("cvt.rn.bf16x2.f32 %0, %1, %2;" : "=r"(hi) : "f"(y), "f"(x));
                float hx = __uint_as_float(hi << 16);
                float hy = __uint_as_float(hi & 0xFFFF0000u);
                unsigned lo;
                asm("cvt.rn.bf16x2.f32 %0, %1, %2;" : "=r"(lo) : "f"(y - hy), "f"(x - hx));
                bBH[row * PITCH + p] = hi;
                bBL[row * PITCH + p] = lo;
            }
        }
        __syncthreads();

        uint32_t baseAH = smem_u32 + ((s & 1) * 4 * TSZ) * 4;
        MMA_STEP(baseAH, baseAH + TSZ * 4, baseAH + 2 * TSZ * 4, baseAH + 3 * TSZ * 4);
        __syncthreads();
    }
#undef STAGE_SC

    // epilogue: store C + per-row (max, sumexp) partials, reduced in smem
    float2* red = (float2*)sm;     // [128][16] = 16 KB, staging buffer reuse
#pragma unroll
    for (int mt = 0; mt < 4; ++mt) {
        int rl0 = m_base + mt * 16 + g;
        int row0 = bm + rl0;
        float m0 = -INFINITY, s0 = 0.f, m1 = -INFINITY, s1 = 0.f;
#pragma unroll
        for (int nt = 0; nt < 4; ++nt) {
            int col0 = bn + n_base + nt * 8 + 2 * tg;
            float v00 = acc[mt][nt][0], v01 = acc[mt][nt][1];
            float v10 = acc[mt][nt][2], v11 = acc[mt][nt][3];
            if (col0 < N) {
                C[(size_t)row0 * N + col0]       = v00;
                C[(size_t)(row0 + 8) * N + col0] = v10;
                float nm0 = fmaxf(m0, v00); s0 = s0 * __expf(m0 - nm0) + __expf(v00 - nm0); m0 = nm0;
                float nm1 = fmaxf(m1, v10); s1 = s1 * __expf(m1 - nm1) + __expf(v10 - nm1); m1 = nm1;
            }
            if (col0 + 1 < N) {
                C[(size_t)row0 * N + col0 + 1]       = v01;
                C[(size_t)(row0 + 8) * N + col0 + 1] = v11;
                float nm0 = fmaxf(m0, v01); s0 = s0 * __expf(m0 - nm0) + __expf(v01 - nm0); m0 = nm0;
                float nm1 = fmaxf(m1, v11); s1 = s1 * __expf(m1 - nm1) + __expf(v11 - nm1); m1 = nm1;
            }
        }
        int slot = warp_n * 4 + tg;
        red[rl0 * 16 + slot]       = make_float2(m0, s0);
        red[(rl0 + 8) * 16 + slot] = make_float2(m1, s1);
    }
    __syncthreads();
    if (tid < 128) {
        float m = -INFINITY, s = 0.f;
#pragma unroll
        for (int k = 0; k < 16; ++k) {
            float2 v = red[tid * 16 + k];
            float nm = fmaxf(m, v.x);
            s = s * __expf(m - nm) + v.y * __expf(v.x - nm);
            m = nm;
        }
        part[(size_t)blockIdx.y * MQ + bm + tid] = make_float2(m, s);
    }
}

// ---------------- attention (reads merged KV, ld=1024) ------------------------
__global__ __launch_bounds__(256)
void attn_kernel(const float* __restrict__ Q,
                 const float* __restrict__ KV,
                 float* __restrict__ out) {
    int blk = blockIdx.x;
    int b = blk / HH, h = blk % HH;

    __shared__ float sQ[NM][DH];
    __shared__ float sS[NM][SC];
    __shared__ float sKV[SC][DH + 1];

    int tid = threadIdx.x;

    for (int e = tid; e < NM * DH; e += 256) {
        int m = e / DH, d0 = e % DH;
        sQ[m][d0] = Q[((size_t)b * NM + m) * DM + h * DH + d0];
    }
    for (int e = tid; e < SC * DH; e += 256) {
        int k = e / DH, d0 = e % DH;
        sKV[k][d0] = KV[((size_t)b * SC + k) * 1024 + h * DH + d0];
    }
    __syncthreads();

    for (int e = tid; e < NM * SC; e += 256) {
        int m = e / SC, k = e % SC;
        float acc = 0.f;
#pragma unroll
        for (int d0 = 0; d0 < DH; ++d0) acc += sQ[m][d0] * sKV[k][d0];
        sS[m][k] = acc;
    }
    __syncthreads();

    int w = tid >> 5, lane = tid & 31;
    for (int m = 2 * w; m < 2 * w + 2; ++m) {
        float vals[4];
        float mx = -INFINITY;
#pragma unroll
        for (int j = 0; j < 4; ++j) {
            vals[j] = sS[m][lane * 4 + j];
            mx = fmaxf(mx, vals[j]);
        }
#pragma unroll
        for (int off = 16; off; off >>= 1)
            mx = fmaxf(mx, __shfl_xor_sync(0xffffffffu, mx, off));
        float sum = 0.f;
#pragma unroll
        for (int j = 0; j < 4; ++j) {
            vals[j] = expf(vals[j] - mx);
            sum += vals[j];
        }
#pragma unroll
        for (int off = 16; off; off >>= 1)
            sum += __shfl_xor_sync(0xffffffffu, sum, off);
        float inv = 1.f / sum;
#pragma unroll
        for (int j = 0; j < 4; ++j) sS[m][lane * 4 + j] = vals[j] * inv;
    }
    __syncthreads();

    for (int e = tid; e < SC * DH; e += 256) {
        int k = e / DH, d0 = e % DH;
        sKV[k][d0] = KV[((size_t)b * SC + k) * 1024 + 512 + h * DH + d0];
    }
    __syncthreads();

    for (int e = tid; e < NM * DH; e += 256) {
        int m = e / DH, d0 = e % DH;
        float acc = 0.f;
#pragma unroll
        for (int k = 0; k < SC; ++k) acc += sS[m][k] * sKV[k][d0];
        out[((size_t)b * NM + m) * DM + h * DH + d0] = acc;
    }
}

// ---------------- fused LSE reduce + subtract (block per row) -----------------
__global__ __launch_bounds__(256)
void lse_sub_kernel(const float2* __restrict__ part, float* __restrict__ out) {
    int row = blockIdx.x;
    __shared__ float rm[256], rs[256];
    int t = threadIdx.x;

    float m = -INFINITY, s = 0.f;
    for (int c = t; c < NCHUNK; c += 256) {
        float2 v = part[(size_t)c * MQ + row];
        float nm = fmaxf(m, v.x);
        s = s * __expf(m - nm) + v.y * __expf(v.x - nm);
        m = nm;
    }
    rm[t] = m; rs[t] = s;
    __syncthreads();
    for (int st = 128; st; st >>= 1) {
        if (t < st) {
            float m2 = rm[t + st], s2 = rs[t + st];
            float nm = fmaxf(rm[t], m2);
            rs[t] = rs[t] * __expf(rm[t] - nm) + s2 * __expf(m2 - nm);
            rm[t] = nm;
        }
        __syncthreads();
    }
    float lse = rm[0] + logf(rs[0]);

    float* p = out + (size_t)row * NC;
    for (int i = t; i < NC; i += 256) p[i] -= lse;
}

// ---------------- launch -----------------------------------------------------
extern "C" void kernel_launch(void* const* d_in, const int* in_sizes, int n_in,
                              void* d_out, int out_size) {
    const int*   mask_pos  = (const int*)d_in[2];
    const int*   mask_curr = (const int*)d_in[3];
    const float* emb       = (const float*)d_in[5];
    const float* c_wq = (const float*)d_in[12];
    const float* c_bq = (const float*)d_in[13];
    const float* c_wk = (const float*)d_in[14];
    const float* c_bk = (const float*)d_in[15];
    const float* c_wv = (const float*)d_in[16];
    const float* c_bv = (const float*)d_in[17];
    const float* t2_w = (const float*)d_in[24];
    const float* t2_b = (const float*)d_in[25];
    float* out = (float*)d_out;

    float *KV, *Qb, *attn, *bKV;
    float2* part;
    cudaGetSymbolAddress((void**)&KV,   g_KV);
    cudaGetSymbolAddress((void**)&Qb,   g_Q);
    cudaGetSymbolAddress((void**)&attn, g_attn);
    cudaGetSymbolAddress((void**)&bKV,  g_bKV);
    cudaGetSymbolAddress((void**)&part, g_part);

    unsigned *currH, *currL, *wkvH, *wkvL, *wqH, *wqL, *t2H, *t2L;
    unsigned *tanhH, *tanhL, *hybH, *hybL;
    cudaGetSymbolAddress((void**)&currH, g_pk_currH);
    cudaGetSymbolAddress((void**)&currL, g_pk_currL);
    cudaGetSymbolAddress((void**)&wkvH,  g_pk_wkvH);
    cudaGetSymbolAddress((void**)&wkvL,  g_pk_wkvL);
    cudaGetSymbolAddress((void**)&wqH,   g_pk_wqH);
    cudaGetSymbolAddress((void**)&wqL,   g_pk_wqL);
    cudaGetSymbolAddress((void**)&t2H,   g_pk_t2H);
    cudaGetSymbolAddress((void**)&t2L,   g_pk_t2L);
    cudaGetSymbolAddress((void**)&tanhH, g_pk_tanhH);
    cudaGetSymbolAddress((void**)&tanhL, g_pk_tanhL);
    cudaGetSymbolAddress((void**)&hybH,  g_pk_hybH);
    cudaGetSymbolAddress((void**)&hybL,  g_pk_hybL);

    const int SMEMB  = 2 * 4 * TSZ * 4;                // 81920 B
    const int SMEMSC = (8 * TSZ + 2 * F32SZ) * 4;      // 114688 B
    cudaFuncSetAttribute(gemm_pk_kernel,
                         cudaFuncAttributeMaxDynamicSharedMemorySize, SMEMB);
    cudaFuncSetAttribute(gemm_pk_qproj_kernel,
                         cudaFuncAttributeMaxDynamicSharedMemorySize, SMEMB);
    cudaFuncSetAttribute(gemm_pk_packout_kernel,
                         cudaFuncAttributeMaxDynamicSharedMemorySize, SMEMB);
    cudaFuncSetAttribute(gemm_score_kernel,
                         cudaFuncAttributeMaxDynamicSharedMemorySize, SMEMSC);

    const long WP = (long)DM * KP2;        // pairs per 512x512 matrix

    // 0: merged wk|wv prepack
    prepack_kv_kernel<<<(int)((2 * WP + 255) / 256), 256>>>(c_wk, c_wv, wkvH, wkvL, WP);
    // 1: merged wq + t2 prepack
    prepack_qt2_kernel<<<(int)((2 * WP + 255) / 256), 256>>>(c_wq, t2_w, wqH, wqL, t2H, t2L, WP);
    // 2: bias concat
    concat_bias_kernel<<<4, 256>>>(c_bk, c_bv, bKV);
    // 3: curr = emb[mask_curr] + PE, packed directly
    gather_pe_pack_kernel<<<(BB * SC * KP2 + 255) / 256, 256>>>(mask_curr, emb,
                                                                currH, currL);
    // 4: Q projection with fused mask gather (independent of KV)
    {
        dim3 g(MQ / 128, DM / 128);
        gemm_pk_qproj_kernel<<<g, 256, SMEMB>>>(mask_pos, currH, currL, wqH, wqL, c_bq, Qb);
    }
    // 5: merged K|V projection [4096, 1024]  (ncu -s 5 captures THIS)
    {
        dim3 g((BB * SC) / 128, 1024 / 128);
        gemm_pk_kernel<<<g, 256, SMEMB>>>(currH, currL, wkvH, wkvL, bKV, KV,
                                          BB * SC, 1024, 1024);
    }

    // attention
    attn_kernel<<<BB * HH, 256>>>(Qb, KV, attn);

    // hyb = tanh(attn) @ t2_w^T + t2_b, emitted directly as packed hi/lo
    prepack_kernel<<<(MQ * KP2 + 255) / 256, 256>>>(attn, tanhH, tanhL, MQ * KP2, 1);
    {
        dim3 g(MQ / 128, DM / 128);
        gemm_pk_packout_kernel<<<g, 256, SMEMB>>>(tanhH, tanhL, t2H, t2L, t2_b,
                                                  hybH, hybL, MQ, DM);
    }

    // scores = hyb @ emb[2:]^T, B converted in-kernel, fused LSE partials
    {
        dim3 g(MQ / 128, NCHUNK);
        gemm_score_kernel<<<g, 256, SMEMSC>>>(hybH, hybL, emb + 2 * DM, out, part, NC);
    }

    // fused lse reduce + subtract
    lse_sub_kernel<<<MQ, 256>>>(part, out);
}